// round 3
// baseline (speedup 1.0000x reference)
#include <cuda_runtime.h>

#define NN   100000
#define D    128
#define EH   600000
#define RRG  8
#define RHET 4
#define EREL 150000

typedef unsigned long long u64;

// ---- scratch (device globals: no cudaMalloc allowed) ----
__device__ float g_h  [NN * D];           // 51.2 MB  layer-1 output (reused per branch)
__device__ float g_agg[NN * D];           // 51.2 MB  aggregation accumulator (L2-resident)
__device__ float g_rb [NN * RRG * D];     // 409.6 MB RGCN pre-transformed H
__device__ float g_hb [NN * RHET * D];    // 204.8 MB hetero per-relation buckets

__device__ __forceinline__ float* selbuf(int w, float* dflt) {
    switch (w) {
        case 1: return g_h;
        case 2: return g_agg;
        case 3: return g_rb;
        case 4: return g_hb;
        default: return dflt;
    }
}

// ---- packed f32x2 helpers (sm_100+ FFMA2 path; ptxas never emits from C++) ----
__device__ __forceinline__ u64 dup2(float a) {
    u64 r; asm("mov.b64 %0, {%1,%1};" : "=l"(r) : "f"(a)); return r;
}
__device__ __forceinline__ float2 unpk2(u64 v) {
    float2 r; asm("mov.b64 {%0,%1}, %2;" : "=f"(r.x), "=f"(r.y) : "l"(v)); return r;
}
__device__ __forceinline__ void fma2(u64& acc, u64 a, u64 b) {
    asm("fma.rn.f32x2 %0, %1, %2, %0;" : "+l"(acc) : "l"(a), "l"(b));
}

// ---------------------------------------------------------------------------
__global__ void __launch_bounds__(256) zero_kernel(int which, int n4) {
    float4* p = (float4*)selbuf(which, nullptr);
    int i = blockIdx.x * blockDim.x + threadIdx.x;
    int stride = gridDim.x * blockDim.x;
    float4 z = make_float4(0.f, 0.f, 0.f, 0.f);
    for (; i < n4; i += stride) p[i] = z;
}

// One warp per edge: gather 128-float row, vector-reduce into destination row.
//   source row index = s*inR + (inR>1 ? rel : 0)
//   dest   row index = d*outR + (outR>1 ? rel : 0)
__global__ void __launch_bounds__(256) scatter_kernel(
        int xWhich, const float* xExt,
        const int* __restrict__ src, const int* __restrict__ dst,
        const int* __restrict__ et, int relDiv,
        int inR, int outR, int outWhich, int E) {
    int gw = (blockIdx.x * blockDim.x + threadIdx.x) >> 5;
    if (gw >= E) return;
    int lane = threadIdx.x & 31;
    const float4* x = (const float4*)selbuf(xWhich, (float*)xExt);
    float4* out = (float4*)selbuf(outWhich, nullptr);
    int s = src[gw];
    int d = dst[gw];
    int r = et ? et[gw] : (relDiv ? (gw / relDiv) : 0);
    size_t sIdx = (size_t)s * inR + (inR > 1 ? r : 0);
    size_t dIdx = (size_t)d * outR + (outR > 1 ? r : 0);
    float4 v = x[sIdx * 32 + lane];
    float4* o = out + dIdx * 32 + lane;
    asm volatile("red.global.add.v4.f32 [%0], {%1,%2,%3,%4};"
                 :: "l"(o), "f"(v.x), "f"(v.y), "f"(v.z), "f"(v.w)
                 : "memory");
}

// ---------------------------------------------------------------------------
// Shared loader: stage a 32x128 A chunk into shared with every element
// duplicated into a packed f32x2, so the inner loop needs no MOVs.
// Thread t: rowblock rb = t>>5 handles rows rb*8..rb*8+7; lane kl = t&31.
__device__ __forceinline__ void load_sAdup(
        u64* sAd, const float* Asrc, int n0, int ldA, int kOff, int t) {
    int kl = t & 31;
    int rb = t >> 5;
#pragma unroll
    for (int i = 0; i < 8; i++) {
        int row = rb * 8 + i;
        const float* ap = Asrc + (size_t)(n0 + row) * ldA + kOff;
#pragma unroll
        for (int j = 0; j < 2; j++) {
            int k2 = 2 * (kl + 32 * j);                 // even k
            float2 v = *(const float2*)(ap + k2);       // LDG.64 coalesced
            sAd[row * 128 + k2]     = dup2(v.x);        // STS.128 (merged)
            sAd[row * 128 + k2 + 1] = dup2(v.y);
        }
    }
}

// Inner product over one 128-k chunk: acc[row][colpair] += A row * W.
__device__ __forceinline__ void mma_chunk(
        u64 acc[8][2], const u64* sArow, const float* __restrict__ Wc, int c4) {
#pragma unroll 4
    for (int k = 0; k < 128; k++) {
        ulonglong2 w2 = *(const ulonglong2*)(Wc + k * 128 + c4 * 4);
#pragma unroll
        for (int r = 0; r < 8; r++) {
            u64 ad = sArow[r * 128 + k];                // LDS.64 broadcast
            fma2(acc[r][0], ad, w2.x);
            fma2(acc[r][1], ad, w2.y);
        }
    }
}

// ---------------------------------------------------------------------------
// Multi-output transform (RGCN): H[(n*R + r)*128 + c] = sum_k X[n,k] W[r,k,c].
// One A-tile staging, R inner-product passes. No bias/activation.
__global__ void __launch_bounds__(128) xform_kernel(
        int aWhich, const float* aExt, int R,
        const float* __restrict__ W, int outWhich) {
    __shared__ u64 sAd[32 * 128];
    const float* A = selbuf(aWhich, (float*)aExt);
    float* out = selbuf(outWhich, nullptr);
    int t = threadIdx.x;
    int c4 = t & 31;
    int rg = t >> 5;
    int n0 = blockIdx.x * 32;

    load_sAdup(sAd, A, n0, 128, 0, t);
    __syncthreads();
    const u64* sArow = sAd + rg * 8 * 128;

    for (int r = 0; r < R; r++) {
        u64 acc[8][2];
#pragma unroll
        for (int i = 0; i < 8; i++) { acc[i][0] = 0ull; acc[i][1] = 0ull; }
        mma_chunk(acc, sArow, W + r * (128 * 128), c4);
#pragma unroll
        for (int rr = 0; rr < 8; rr++) {
            int n = n0 + rg * 8 + rr;
            float2 p0 = unpk2(acc[rr][0]);
            float2 p1 = unpk2(acc[rr][1]);
            float4 o = make_float4(p0.x, p0.y, p1.x, p1.y);
            *(float4*)(out + ((size_t)n * R + r) * 128 + c4 * 4) = o;
        }
    }
}

// ---------------------------------------------------------------------------
// Fused multi-chunk GEMM + bias + tanh.
//   PCT=0: out = tanh(sum_ch A_ch @ W_ch + add + b)
//   PCT=1: out = (1/nChunks) * sum_ch tanh(A_ch @ W_ch + b_ch)   (hetero mean)
template <int PCT>
__global__ void __launch_bounds__(128) gemm_kernel(
        int aWhich, const float* aExt, int nChunks,
        const float* __restrict__ W,
        int addWhich,
        const float* __restrict__ b,
        float* outExt, int outWhich) {
    __shared__ u64 sAd[32 * 128];
    const float* A = selbuf(aWhich, (float*)aExt);
    float* out = selbuf(outWhich, outExt);
    int t = threadIdx.x;
    int c4 = t & 31;
    int rg = t >> 5;
    int n0 = blockIdx.x * 32;
    int ldA = nChunks * 128;

    u64   acc[8][2];
    float fin[8][4];
#pragma unroll
    for (int r = 0; r < 8; r++) {
        acc[r][0] = 0ull; acc[r][1] = 0ull;
#pragma unroll
        for (int j = 0; j < 4; j++) fin[r][j] = 0.f;
    }

    for (int ch = 0; ch < nChunks; ch++) {
        __syncthreads();
        load_sAdup(sAd, A, n0, ldA, ch * 128, t);
        __syncthreads();
        mma_chunk(acc, sAd + rg * 8 * 128, W + ch * (128 * 128), c4);

        if (PCT) {
            float4 b4 = *(const float4*)(b + ch * 128 + c4 * 4);
#pragma unroll
            for (int r = 0; r < 8; r++) {
                float2 p0 = unpk2(acc[r][0]);
                float2 p1 = unpk2(acc[r][1]);
                fin[r][0] += tanhf(p0.x + b4.x);
                fin[r][1] += tanhf(p0.y + b4.y);
                fin[r][2] += tanhf(p1.x + b4.z);
                fin[r][3] += tanhf(p1.y + b4.w);
                acc[r][0] = 0ull; acc[r][1] = 0ull;
            }
        }
    }

    float scale = PCT ? (1.0f / (float)nChunks) : 1.0f;
    float4 b4;
    const float* add = (!PCT && addWhich) ? selbuf(addWhich, nullptr) : nullptr;
    if (!PCT) b4 = *(const float4*)(b + c4 * 4);
#pragma unroll
    for (int r = 0; r < 8; r++) {
        int n = n0 + rg * 8 + r;
        float4 o;
        if (PCT) {
            o.x = fin[r][0] * scale; o.y = fin[r][1] * scale;
            o.z = fin[r][2] * scale; o.w = fin[r][3] * scale;
        } else {
            float2 p0 = unpk2(acc[r][0]);
            float2 p1 = unpk2(acc[r][1]);
            float4 a4 = make_float4(0.f, 0.f, 0.f, 0.f);
            if (add) a4 = *(const float4*)(add + (size_t)n * 128 + c4 * 4);
            o.x = tanhf(p0.x + b4.x + a4.x);
            o.y = tanhf(p0.y + b4.y + a4.y);
            o.z = tanhf(p1.x + b4.z + a4.z);
            o.w = tanhf(p1.y + b4.w + a4.w);
        }
        *(float4*)(out + (size_t)n * 128 + c4 * 4) = o;
    }
}

// ---------------------------------------------------------------------------
extern "C" void kernel_launch(void* const* d_in, const int* in_sizes, int n_in,
                              void* d_out, int out_size) {
    const int*   gcn_src1 = (const int*)d_in[0];
    const int*   gcn_dst1 = (const int*)d_in[1];
    const int*   gcn_src2 = (const int*)d_in[2];
    const int*   gcn_dst2 = (const int*)d_in[3];
    const int*   rg_src1  = (const int*)d_in[4];
    const int*   rg_dst1  = (const int*)d_in[5];
    const int*   rg_et1   = (const int*)d_in[6];
    const int*   rg_src2  = (const int*)d_in[7];
    const int*   rg_dst2  = (const int*)d_in[8];
    const int*   rg_et2   = (const int*)d_in[9];
    const int*   het_src1 = (const int*)d_in[10];
    const int*   het_dst1 = (const int*)d_in[11];
    const int*   het_src2 = (const int*)d_in[12];
    const int*   het_dst2 = (const int*)d_in[13];
    const float* emb      = (const float*)d_in[14];
    const float* gcn_W1   = (const float*)d_in[15];
    const float* gcn_b1   = (const float*)d_in[16];
    const float* gcn_W2   = (const float*)d_in[17];
    const float* gcn_b2   = (const float*)d_in[18];
    const float* rg_W1    = (const float*)d_in[19];
    const float* rg_loop1 = (const float*)d_in[20];
    const float* rg_b1    = (const float*)d_in[21];
    const float* rg_W2    = (const float*)d_in[22];
    const float* rg_loop2 = (const float*)d_in[23];
    const float* rg_b2    = (const float*)d_in[24];
    const float* het_W1   = (const float*)d_in[25];
    const float* het_b1   = (const float*)d_in[26];
    const float* het_W2   = (const float*)d_in[27];
    const float* het_b2   = (const float*)d_in[28];

    float* out_hcf = (float*)d_out;
    float* out_hc  = out_hcf + (size_t)NN * D;
    float* out_hs  = out_hcf + (size_t)2 * NN * D;

    const int ZB = 256, ZG = 2048;
    const int sgrid = EH / 8;     // 8 edges (warps) per 256-thread block
    const int ggrid = NN / 32;    // 3125 blocks

    // ---- GCN branch ----
    zero_kernel<<<ZG, ZB>>>(2, NN * 32);
    scatter_kernel<<<sgrid, 256>>>(0, emb, gcn_src1, gcn_dst1, nullptr, 0, 1, 1, 2, EH);
    gemm_kernel<0><<<ggrid, 128>>>(2, nullptr, 1, gcn_W1, 0, gcn_b1, nullptr, 1);
    zero_kernel<<<ZG, ZB>>>(2, NN * 32);
    scatter_kernel<<<sgrid, 256>>>(1, nullptr, gcn_src2, gcn_dst2, nullptr, 0, 1, 1, 2, EH);
    gemm_kernel<0><<<ggrid, 128>>>(2, nullptr, 1, gcn_W2, 0, gcn_b2, out_hcf, 0);

    // ---- RGCN branch (transform-first) ----
    xform_kernel<<<ggrid, 128>>>(0, emb, RRG, rg_W1, 3);
    zero_kernel<<<ZG, ZB>>>(2, NN * 32);
    scatter_kernel<<<sgrid, 256>>>(3, nullptr, rg_src1, rg_dst1, rg_et1, 0, RRG, 1, 2, EH);
    gemm_kernel<0><<<ggrid, 128>>>(0, emb, 1, rg_loop1, 2, rg_b1, nullptr, 1);

    xform_kernel<<<ggrid, 128>>>(1, nullptr, RRG, rg_W2, 3);
    zero_kernel<<<ZG, ZB>>>(2, NN * 32);
    scatter_kernel<<<sgrid, 256>>>(3, nullptr, rg_src2, rg_dst2, rg_et2, 0, RRG, 1, 2, EH);
    gemm_kernel<0><<<ggrid, 128>>>(1, nullptr, 1, rg_loop2, 2, rg_b2, out_hc, 0);

    // ---- Hetero branch ----
    zero_kernel<<<ZG, ZB>>>(4, NN * RHET * 32);
    scatter_kernel<<<sgrid, 256>>>(0, emb, het_src1, het_dst1, nullptr, EREL, 1, RHET, 4, EH);
    gemm_kernel<1><<<ggrid, 128>>>(4, nullptr, RHET, het_W1, 0, het_b1, nullptr, 1);
    zero_kernel<<<ZG, ZB>>>(4, NN * RHET * 32);
    scatter_kernel<<<sgrid, 256>>>(1, nullptr, het_src2, het_dst2, nullptr, EREL, 1, RHET, 4, EH);
    gemm_kernel<1><<<ggrid, 128>>>(4, nullptr, RHET, het_W2, 0, het_b2, out_hs, 0);
}

// round 4
// speedup vs baseline: 1.0422x; 1.0422x over previous
#include <cuda_runtime.h>

#define NN   100000
#define D    128
#define EH   600000
#define RRG  8
#define RHET 4
#define EREL 150000

typedef unsigned long long u64;

// ---- scratch (device globals: no cudaMalloc allowed) ----
__device__ float g_h  [NN * D];           // 51.2 MB  layer-1 output (reused per branch)
__device__ float g_agg[NN * D];           // 51.2 MB  aggregation accumulator (L2-resident)
__device__ float g_rb [NN * RRG * D];     // 409.6 MB RGCN per-relation buckets
__device__ float g_hb [NN * RHET * D];    // 204.8 MB hetero per-relation buckets

__device__ __forceinline__ float* selbuf(int w, float* dflt) {
    switch (w) {
        case 1: return g_h;
        case 2: return g_agg;
        case 3: return g_rb;
        case 4: return g_hb;
        default: return dflt;
    }
}

// ---- packed f32x2 helpers (sm_100+ FFMA2 path; ptxas never emits from C++) ----
__device__ __forceinline__ u64 dup2(float a) {
    u64 r; asm("mov.b64 %0, {%1,%1};" : "=l"(r) : "f"(a)); return r;
}
__device__ __forceinline__ float2 unpk2(u64 v) {
    float2 r; asm("mov.b64 {%0,%1}, %2;" : "=f"(r.x), "=f"(r.y) : "l"(v)); return r;
}
__device__ __forceinline__ void fma2(u64& acc, u64 a, u64 b) {
    asm("fma.rn.f32x2 %0, %1, %2, %0;" : "+l"(acc) : "l"(a), "l"(b));
}

// ---------------------------------------------------------------------------
__global__ void __launch_bounds__(256) zero_kernel(int which, int n4) {
    float4* p = (float4*)selbuf(which, nullptr);
    int i = blockIdx.x * blockDim.x + threadIdx.x;
    int stride = gridDim.x * blockDim.x;
    float4 z = make_float4(0.f, 0.f, 0.f, 0.f);
    for (; i < n4; i += stride) p[i] = z;
}

// One warp per edge: gather 128-float row from a small (L2-resident) source,
// vector-reduce into destination row (fire-and-forget red).
//   dest row index = d*outR + (outR>1 ? rel : 0)
__global__ void __launch_bounds__(256) scatter_kernel(
        int xWhich, const float* xExt,
        const int* __restrict__ src, const int* __restrict__ dst,
        const int* __restrict__ et, int relDiv,
        int outR, int outWhich, int E) {
    int gw = (blockIdx.x * blockDim.x + threadIdx.x) >> 5;
    if (gw >= E) return;
    int lane = threadIdx.x & 31;
    const float4* x = (const float4*)selbuf(xWhich, (float*)xExt);
    float4* out = (float4*)selbuf(outWhich, nullptr);
    int s = src[gw];
    int d = dst[gw];
    int r = et ? et[gw] : (relDiv ? (gw / relDiv) : 0);
    size_t dIdx = (size_t)d * outR + (outR > 1 ? r : 0);
    float4 v = x[(size_t)s * 32 + lane];
    float4* o = out + dIdx * 32 + lane;
    asm volatile("red.global.add.v4.f32 [%0], {%1,%2,%3,%4};"
                 :: "l"(o), "f"(v.x), "f"(v.y), "f"(v.z), "f"(v.w)
                 : "memory");
}

// ---------------------------------------------------------------------------
// Shared loader: stage a 32x128 A chunk into shared with every element
// duplicated into a packed f32x2, so the mma inner loop needs no MOVs.
__device__ __forceinline__ void load_sAdup(
        u64* sAd, const float* Asrc, int n0, int ldA, int kOff, int t) {
    int kl = t & 31;
    int rb = t >> 5;
#pragma unroll
    for (int i = 0; i < 8; i++) {
        int row = rb * 8 + i;
        const float* ap = Asrc + (size_t)(n0 + row) * ldA + kOff;
#pragma unroll
        for (int j = 0; j < 2; j++) {
            int k2 = 2 * (kl + 32 * j);                 // even k
            float2 v = *(const float2*)(ap + k2);       // LDG.64 coalesced
            sAd[row * 128 + k2]     = dup2(v.x);        // STS.128 (merged)
            sAd[row * 128 + k2 + 1] = dup2(v.y);
        }
    }
}

// Inner product over one 128-k chunk: acc[row][colpair] += A row * W.
__device__ __forceinline__ void mma_chunk(
        u64 acc[8][2], const u64* sArow, const float* __restrict__ Wc, int c4) {
#pragma unroll 4
    for (int k = 0; k < 128; k++) {
        ulonglong2 w2 = *(const ulonglong2*)(Wc + k * 128 + c4 * 4);
#pragma unroll
        for (int r = 0; r < 8; r++) {
            u64 ad = sArow[r * 128 + k];                // LDS.64 broadcast
            fma2(acc[r][0], ad, w2.x);
            fma2(acc[r][1], ad, w2.y);
        }
    }
}

// ---------------------------------------------------------------------------
// Fused multi-chunk GEMM + bias + tanh.
//   A is [N, nChunks*128] (bucket layout), W is [nChunks,128,128] contiguous.
//   Optional self-loop term X[N,128] @ Wl appended as an extra chunk (RGCN).
//   PCT=0: out = tanh(sum_ch A_ch @ W_ch (+ X@Wl) + b)
//   PCT=1: out = (1/nChunks) * sum_ch tanh(A_ch @ W_ch + b_ch)   (hetero mean)
template <int PCT>
__global__ void __launch_bounds__(128) gemm_kernel(
        int aWhich, const float* aExt, int nChunks,
        const float* __restrict__ W,
        int xWhich, const float* xExt, const float* __restrict__ Wl,
        const float* __restrict__ b,
        float* outExt, int outWhich) {
    __shared__ u64 sAd[32 * 128];
    const float* A = selbuf(aWhich, (float*)aExt);
    const float* X = (Wl != nullptr) ? selbuf(xWhich, (float*)xExt) : nullptr;
    float* out = selbuf(outWhich, outExt);
    int t  = threadIdx.x;
    int c4 = t & 31;
    int rg = t >> 5;
    int n0 = blockIdx.x * 32;
    int ldA = nChunks * 128;

    u64   acc[8][2];
    float fin[8][4];
#pragma unroll
    for (int r = 0; r < 8; r++) {
        acc[r][0] = 0ull; acc[r][1] = 0ull;
#pragma unroll
        for (int j = 0; j < 4; j++) fin[r][j] = 0.f;
    }

    int totChunks = nChunks + (X ? 1 : 0);
    for (int ch = 0; ch < totChunks; ch++) {
        const float* Asrc; int ld; int kOff; const float* Wc;
        if (ch < nChunks) { Asrc = A; ld = ldA; kOff = ch * 128; Wc = W + ch * (128 * 128); }
        else              { Asrc = X; ld = 128; kOff = 0;        Wc = Wl; }

        __syncthreads();
        load_sAdup(sAd, Asrc, n0, ld, kOff, t);
        __syncthreads();
        mma_chunk(acc, sAd + rg * 8 * 128, Wc, c4);

        if (PCT) {
            float4 b4 = *(const float4*)(b + ch * 128 + c4 * 4);
#pragma unroll
            for (int r = 0; r < 8; r++) {
                float2 p0 = unpk2(acc[r][0]);
                float2 p1 = unpk2(acc[r][1]);
                fin[r][0] += tanhf(p0.x + b4.x);
                fin[r][1] += tanhf(p0.y + b4.y);
                fin[r][2] += tanhf(p1.x + b4.z);
                fin[r][3] += tanhf(p1.y + b4.w);
                acc[r][0] = 0ull; acc[r][1] = 0ull;
            }
        }
    }

    float scale = PCT ? (1.0f / (float)nChunks) : 1.0f;
    float4 b4;
    if (!PCT) b4 = *(const float4*)(b + c4 * 4);
#pragma unroll
    for (int r = 0; r < 8; r++) {
        int n = n0 + rg * 8 + r;
        float4 o;
        if (PCT) {
            o.x = fin[r][0] * scale; o.y = fin[r][1] * scale;
            o.z = fin[r][2] * scale; o.w = fin[r][3] * scale;
        } else {
            float2 p0 = unpk2(acc[r][0]);
            float2 p1 = unpk2(acc[r][1]);
            o.x = tanhf(p0.x + b4.x); o.y = tanhf(p0.y + b4.y);
            o.z = tanhf(p1.x + b4.z); o.w = tanhf(p1.y + b4.w);
        }
        *(float4*)(out + (size_t)n * 128 + c4 * 4) = o;
    }
}

// ---------------------------------------------------------------------------
extern "C" void kernel_launch(void* const* d_in, const int* in_sizes, int n_in,
                              void* d_out, int out_size) {
    const int*   gcn_src1 = (const int*)d_in[0];
    const int*   gcn_dst1 = (const int*)d_in[1];
    const int*   gcn_src2 = (const int*)d_in[2];
    const int*   gcn_dst2 = (const int*)d_in[3];
    const int*   rg_src1  = (const int*)d_in[4];
    const int*   rg_dst1  = (const int*)d_in[5];
    const int*   rg_et1   = (const int*)d_in[6];
    const int*   rg_src2  = (const int*)d_in[7];
    const int*   rg_dst2  = (const int*)d_in[8];
    const int*   rg_et2   = (const int*)d_in[9];
    const int*   het_src1 = (const int*)d_in[10];
    const int*   het_dst1 = (const int*)d_in[11];
    const int*   het_src2 = (const int*)d_in[12];
    const int*   het_dst2 = (const int*)d_in[13];
    const float* emb      = (const float*)d_in[14];
    const float* gcn_W1   = (const float*)d_in[15];
    const float* gcn_b1   = (const float*)d_in[16];
    const float* gcn_W2   = (const float*)d_in[17];
    const float* gcn_b2   = (const float*)d_in[18];
    const float* rg_W1    = (const float*)d_in[19];
    const float* rg_loop1 = (const float*)d_in[20];
    const float* rg_b1    = (const float*)d_in[21];
    const float* rg_W2    = (const float*)d_in[22];
    const float* rg_loop2 = (const float*)d_in[23];
    const float* rg_b2    = (const float*)d_in[24];
    const float* het_W1   = (const float*)d_in[25];
    const float* het_b1   = (const float*)d_in[26];
    const float* het_W2   = (const float*)d_in[27];
    const float* het_b2   = (const float*)d_in[28];

    float* out_hcf = (float*)d_out;
    float* out_hc  = out_hcf + (size_t)NN * D;
    float* out_hs  = out_hcf + (size_t)2 * NN * D;

    const int ZB = 256, ZG = 2048;
    const int sgrid = EH / 8;     // 8 edges (warps) per 256-thread block
    const int ggrid = NN / 32;    // 3125 blocks

    // ---- GCN branch ----
    zero_kernel<<<ZG, ZB>>>(2, NN * 32);
    scatter_kernel<<<sgrid, 256>>>(0, emb, gcn_src1, gcn_dst1, nullptr, 0, 1, 2, EH);
    gemm_kernel<0><<<ggrid, 128>>>(2, nullptr, 1, gcn_W1, 0, nullptr, nullptr, gcn_b1, nullptr, 1);
    zero_kernel<<<ZG, ZB>>>(2, NN * 32);
    scatter_kernel<<<sgrid, 256>>>(1, nullptr, gcn_src2, gcn_dst2, nullptr, 0, 1, 2, EH);
    gemm_kernel<0><<<ggrid, 128>>>(2, nullptr, 1, gcn_W2, 0, nullptr, nullptr, gcn_b2, out_hcf, 0);

    // ---- RGCN branch (bucket scatter + multi-chunk GEMM + self-loop chunk) ----
    zero_kernel<<<ZG, ZB>>>(3, NN * RRG * 32);
    scatter_kernel<<<sgrid, 256>>>(0, emb, rg_src1, rg_dst1, rg_et1, 0, RRG, 3, EH);
    gemm_kernel<0><<<ggrid, 128>>>(3, nullptr, RRG, rg_W1, 0, emb, rg_loop1, rg_b1, nullptr, 1);
    zero_kernel<<<ZG, ZB>>>(3, NN * RRG * 32);
    scatter_kernel<<<sgrid, 256>>>(1, nullptr, rg_src2, rg_dst2, rg_et2, 0, RRG, 3, EH);
    gemm_kernel<0><<<ggrid, 128>>>(3, nullptr, RRG, rg_W2, 1, nullptr, rg_loop2, rg_b2, out_hc, 0);

    // ---- Hetero branch ----
    zero_kernel<<<ZG, ZB>>>(4, NN * RHET * 32);
    scatter_kernel<<<sgrid, 256>>>(0, emb, het_src1, het_dst1, nullptr, EREL, RHET, 4, EH);
    gemm_kernel<1><<<ggrid, 128>>>(4, nullptr, RHET, het_W1, 0, nullptr, nullptr, het_b1, nullptr, 1);
    zero_kernel<<<ZG, ZB>>>(4, NN * RHET * 32);
    scatter_kernel<<<sgrid, 256>>>(1, nullptr, het_src2, het_dst2, nullptr, EREL, RHET, 4, EH);
    gemm_kernel<1><<<ggrid, 128>>>(4, nullptr, RHET, het_W2, 0, nullptr, nullptr, het_b2, out_hs, 0);
}

// round 6
// speedup vs baseline: 1.6974x; 1.6287x over previous
#include <cuda_runtime.h>
#include <cuda_bf16.h>
#include <cstdint>

#define NN   100000
#define D    128
#define EH   600000
#define RRG  8
#define RHET 4
#define EREL 150000

// ---- scratch (device globals: no cudaMalloc allowed) ----
__device__ float g_h  [NN * D];                     // 51.2 MB
__device__ float g_agg[NN * D];                     // 51.2 MB
__device__ float g_rb [(size_t)NN * RRG * D];       // 409.6 MB
__device__ float g_hb [(size_t)NN * RHET * D];      // 204.8 MB
// 28 weight matrices, each: bf16 hi block [128k][144] then lo block, 73728 B
#define WSTRIDE 73728
__device__ unsigned char g_wprep[28 * WSTRIDE];

__device__ __forceinline__ float* selbuf(int w, float* dflt) {
    switch (w) {
        case 1: return g_h;
        case 2: return g_agg;
        case 3: return g_rb;
        case 4: return g_hb;
        default: return dflt;
    }
}

// ============================ PTX helpers ==================================
__device__ __forceinline__ uint32_t smem_u32(const void* p) {
    uint32_t a;
    asm("{ .reg .u64 t; cvta.to.shared.u64 t, %1; cvt.u32.u64 %0, t; }" : "=r"(a) : "l"(p));
    return a;
}
__device__ __forceinline__ void ldsm4(uint32_t a, uint32_t* r) {
    asm volatile("ldmatrix.sync.aligned.m8n8.x4.shared.b16 {%0,%1,%2,%3}, [%4];"
                 : "=r"(r[0]), "=r"(r[1]), "=r"(r[2]), "=r"(r[3]) : "r"(a));
}
__device__ __forceinline__ void ldsm4t(uint32_t a, uint32_t* r) {
    asm volatile("ldmatrix.sync.aligned.m8n8.x4.trans.shared.b16 {%0,%1,%2,%3}, [%4];"
                 : "=r"(r[0]), "=r"(r[1]), "=r"(r[2]), "=r"(r[3]) : "r"(a));
}
__device__ __forceinline__ void mma_bf16(float* d, const uint32_t* a, const uint32_t* b) {
    asm volatile(
        "mma.sync.aligned.m16n8k16.row.col.f32.bf16.bf16.f32 "
        "{%0,%1,%2,%3}, {%4,%5,%6,%7}, {%8,%9}, {%0,%1,%2,%3};"
        : "+f"(d[0]), "+f"(d[1]), "+f"(d[2]), "+f"(d[3])
        : "r"(a[0]), "r"(a[1]), "r"(a[2]), "r"(a[3]), "r"(b[0]), "r"(b[1]));
}
__device__ __forceinline__ uint32_t pk_bf16x2(float lo, float hi) {
    uint32_t r;
    asm("cvt.rn.bf16x2.f32 %0, %1, %2;" : "=r"(r) : "f"(hi), "f"(lo));
    return r;
}
__device__ __forceinline__ float bfbits2f(uint32_t b16) { return __uint_as_float(b16 << 16); }

// ============================ simple kernels ===============================
__global__ void __launch_bounds__(256) zero_kernel(int which, int n4) {
    float4* p = (float4*)selbuf(which, nullptr);
    int i = blockIdx.x * blockDim.x + threadIdx.x;
    int stride = gridDim.x * blockDim.x;
    float4 z = make_float4(0.f, 0.f, 0.f, 0.f);
    for (; i < n4; i += stride) p[i] = z;
}

__global__ void __launch_bounds__(256) scatter_kernel(
        int xWhich, const float* xExt,
        const int* __restrict__ src, const int* __restrict__ dst,
        const int* __restrict__ et, int relDiv,
        int outR, int outWhich, int E) {
    int gw = (blockIdx.x * blockDim.x + threadIdx.x) >> 5;
    if (gw >= E) return;
    int lane = threadIdx.x & 31;
    const float4* x = (const float4*)selbuf(xWhich, (float*)xExt);
    float4* out = (float4*)selbuf(outWhich, nullptr);
    int s = src[gw];
    int d = dst[gw];
    int r = et ? et[gw] : (relDiv ? (gw / relDiv) : 0);
    size_t dIdx = (size_t)d * outR + (outR > 1 ? r : 0);
    float4 v = x[(size_t)s * 32 + lane];
    float4* o = out + dIdx * 32 + lane;
    asm volatile("red.global.add.v4.f32 [%0], {%1,%2,%3,%4};"
                 :: "l"(o), "f"(v.x), "f"(v.y), "f"(v.z), "f"(v.w)
                 : "memory");
}

// ============================ weight prep ==================================
// For each of 28 fp32 [128k x 128c] matrices: split into bf16 hi/lo, stored
// row-major [k][c] with row stride 144 elements (288 B, conflict-free ldmatrix).
__global__ void __launch_bounds__(128) prep_weights(
        const float* gcn_W1, const float* gcn_W2,
        const float* rg_W1, const float* rg_loop1,
        const float* rg_W2, const float* rg_loop2,
        const float* het_W1, const float* het_W2) {
    int blk = blockIdx.x;
    const float* W;
    if      (blk == 0)  W = gcn_W1;
    else if (blk == 1)  W = gcn_W2;
    else if (blk < 10)  W = rg_W1 + (size_t)(blk - 2) * 16384;
    else if (blk == 10) W = rg_loop1;
    else if (blk < 19)  W = rg_W2 + (size_t)(blk - 11) * 16384;
    else if (blk == 19) W = rg_loop2;
    else if (blk < 24)  W = het_W1 + (size_t)(blk - 20) * 16384;
    else                W = het_W2 + (size_t)(blk - 24) * 16384;

    __nv_bfloat16* dh = (__nv_bfloat16*)(g_wprep + (size_t)blk * WSTRIDE);
    __nv_bfloat16* dl = dh + 128 * 144;
    int c = threadIdx.x;
    for (int k = 0; k < 128; k++) {
        float w = W[k * 128 + c];
        __nv_bfloat16 h = __float2bfloat16(w);
        __nv_bfloat16 l = __float2bfloat16(w - __bfloat162float(h));
        dh[k * 144 + c] = h;
        dl[k * 144 + c] = l;
    }
}

// ============================ HMMA GEMM ====================================
// 512 threads, 16 warps. CTA tile: 128 rows x 128 cols, K accumulated over
// nChunks (+ optional self-loop chunk). 3-term bf16 split, fp32 register acc.
// Warp (wr = wid&7, wc = wid>>3): rows wr*16..+16, cols wc*64..+64.
//   PCT=0: out = tanh(sum_ch A_ch @ W_ch (+ X@Wl) + b)
//   PCT=1: out = (1/nChunks) * sum_ch tanh(A_ch @ W_ch + b_ch)
#define SM_AH 0
#define SM_AL 36864
#define SM_WH 73728
#define SM_WL 110592
#define SMEM_BYTES 147456

template <int PCT>
__global__ void __launch_bounds__(512) tc_gemm(
        int aWhich, const float* aExt, int nChunks, int wBase,
        int xWhich, const float* xExt, int xWIdx,
        const float* __restrict__ b,
        float* outExt, int outWhich) {
    extern __shared__ unsigned char smem[];
    uint32_t sb = smem_u32(smem);
    int t = threadIdx.x, wid = t >> 5, lane = t & 31;
    int wr = wid & 7, wc = wid >> 3;
    int n0 = blockIdx.x * 128;

    const float* A = selbuf(aWhich, (float*)aExt);
    const float* X = (xWIdx >= 0) ? selbuf(xWhich, (float*)xExt) : nullptr;
    float* out = selbuf(outWhich, outExt);

    float acc[8][4];
    float fin[8][4];
#pragma unroll
    for (int i = 0; i < 8; i++)
#pragma unroll
        for (int j = 0; j < 4; j++) { acc[i][j] = 0.f; fin[i][j] = 0.f; }

    int ldA = nChunks * 128;
    int tot = nChunks + (X ? 1 : 0);

    // per-lane ldmatrix address pieces (bytes)
    uint32_t lmrow = (uint32_t)(lane & 15) * 288 + (uint32_t)(lane >> 4) * 16;
    uint32_t aAddrBase = sb + (uint32_t)wr * 4608 + lmrow;   // + term_off + ks*32
    uint32_t bAddrBase = sb + lmrow + (uint32_t)wc * 128;    // + term_off + ks*4608 + g*32

    for (int ch = 0; ch < tot; ch++) {
        const float* Asrc; int ld, kOff, wIdx;
        if (ch < nChunks) { Asrc = A; ld = ldA; kOff = ch * 128; wIdx = wBase + ch; }
        else              { Asrc = X; ld = 128; kOff = 0;        wIdx = xWIdx; }

        __syncthreads();
        // ---- copy pre-split W image (hi+lo, 73728 B) ----
        {
            const uint4* ws = (const uint4*)(g_wprep + (size_t)wIdx * WSTRIDE);
            uint4* wd = (uint4*)(smem + SM_WH);
#pragma unroll 9
            for (int i = t; i < 4608; i += 512) wd[i] = ws[i];
        }
        // ---- stage A: fp32 -> bf16 hi/lo, padded rows ----
#pragma unroll
        for (int i = 0; i < 8; i++) {
            int f = t + i * 512;
            int row = f >> 5, c4 = f & 31;
            int rc = n0 + row; if (rc > NN - 1) rc = NN - 1;
            float4 v = *(const float4*)(Asrc + (size_t)rc * ld + kOff + c4 * 4);
            uint32_t h01 = pk_bf16x2(v.x, v.y);
            uint32_t h23 = pk_bf16x2(v.z, v.w);
            uint32_t l01 = pk_bf16x2(v.x - bfbits2f(h01 & 0xFFFFu),
                                     v.y - bfbits2f(h01 >> 16));
            uint32_t l23 = pk_bf16x2(v.z - bfbits2f(h23 & 0xFFFFu),
                                     v.w - bfbits2f(h23 >> 16));
            uint32_t off = (uint32_t)row * 288 + (uint32_t)c4 * 8;
            *(uint2*)(smem + SM_AH + off) = make_uint2(h01, h23);
            *(uint2*)(smem + SM_AL + off) = make_uint2(l01, l23);
        }
        __syncthreads();

        // ---- compute: 3-term bf16 split ----
#pragma unroll
        for (int ks = 0; ks < 8; ks++) {
            uint32_t ah[4], al[4];
            ldsm4(aAddrBase + SM_AH + ks * 32, ah);
            ldsm4(aAddrBase + SM_AL + ks * 32, al);
#pragma unroll
            for (int g = 0; g < 4; g++) {
                uint32_t bh[4], bl[4];
                uint32_t baddr = bAddrBase + (uint32_t)ks * 4608 + (uint32_t)g * 32;
                ldsm4t(baddr + SM_WH, bh);
                ldsm4t(baddr + SM_WL, bl);
                mma_bf16(acc[g * 2],     ah, bh);
                mma_bf16(acc[g * 2 + 1], ah, bh + 2);
                mma_bf16(acc[g * 2],     al, bh);
                mma_bf16(acc[g * 2 + 1], al, bh + 2);
                mma_bf16(acc[g * 2],     ah, bl);
                mma_bf16(acc[g * 2 + 1], ah, bl + 2);
            }
        }

        if (PCT) {
#pragma unroll
            for (int nt = 0; nt < 8; nt++) {
                int col = wc * 64 + nt * 8 + (lane & 3) * 2;
                float2 bb = *(const float2*)(b + ch * 128 + col);
                fin[nt][0] += tanhf(acc[nt][0] + bb.x);
                fin[nt][1] += tanhf(acc[nt][1] + bb.y);
                fin[nt][2] += tanhf(acc[nt][2] + bb.x);
                fin[nt][3] += tanhf(acc[nt][3] + bb.y);
                acc[nt][0] = acc[nt][1] = acc[nt][2] = acc[nt][3] = 0.f;
            }
        }
    }

    // ---- epilogue ----
    int r0 = n0 + wr * 16 + (lane >> 2);
    int r1 = r0 + 8;
    if (!PCT) {
#pragma unroll
        for (int nt = 0; nt < 8; nt++) {
            int col = wc * 64 + nt * 8 + (lane & 3) * 2;
            float2 bb = *(const float2*)(b + col);
            if (r0 < NN) {
                float2 o = make_float2(tanhf(acc[nt][0] + bb.x), tanhf(acc[nt][1] + bb.y));
                *(float2*)(out + (size_t)r0 * 128 + col) = o;
            }
            if (r1 < NN) {
                float2 o = make_float2(tanhf(acc[nt][2] + bb.x), tanhf(acc[nt][3] + bb.y));
                *(float2*)(out + (size_t)r1 * 128 + col) = o;
            }
        }
    } else {
        float s = 1.0f / (float)nChunks;
#pragma unroll
        for (int nt = 0; nt < 8; nt++) {
            int col = wc * 64 + nt * 8 + (lane & 3) * 2;
            if (r0 < NN) {
                float2 o = make_float2(fin[nt][0] * s, fin[nt][1] * s);
                *(float2*)(out + (size_t)r0 * 128 + col) = o;
            }
            if (r1 < NN) {
                float2 o = make_float2(fin[nt][2] * s, fin[nt][3] * s);
                *(float2*)(out + (size_t)r1 * 128 + col) = o;
            }
        }
    }
}

// ---------------------------------------------------------------------------
extern "C" void kernel_launch(void* const* d_in, const int* in_sizes, int n_in,
                              void* d_out, int out_size) {
    const int*   gcn_src1 = (const int*)d_in[0];
    const int*   gcn_dst1 = (const int*)d_in[1];
    const int*   gcn_src2 = (const int*)d_in[2];
    const int*   gcn_dst2 = (const int*)d_in[3];
    const int*   rg_src1  = (const int*)d_in[4];
    const int*   rg_dst1  = (const int*)d_in[5];
    const int*   rg_et1   = (const int*)d_in[6];
    const int*   rg_src2  = (const int*)d_in[7];
    const int*   rg_dst2  = (const int*)d_in[8];
    const int*   rg_et2   = (const int*)d_in[9];
    const int*   het_src1 = (const int*)d_in[10];
    const int*   het_dst1 = (const int*)d_in[11];
    const int*   het_src2 = (const int*)d_in[12];
    const int*   het_dst2 = (const int*)d_in[13];
    const float* emb      = (const float*)d_in[14];
    const float* gcn_W1   = (const float*)d_in[15];
    const float* gcn_b1   = (const float*)d_in[16];
    const float* gcn_W2   = (const float*)d_in[17];
    const float* gcn_b2   = (const float*)d_in[18];
    const float* rg_W1    = (const float*)d_in[19];
    const float* rg_loop1 = (const float*)d_in[20];
    const float* rg_b1    = (const float*)d_in[21];
    const float* rg_W2    = (const float*)d_in[22];
    const float* rg_loop2 = (const float*)d_in[23];
    const float* rg_b2    = (const float*)d_in[24];
    const float* het_W1   = (const float*)d_in[25];
    const float* het_b1   = (const float*)d_in[26];
    const float* het_W2   = (const float*)d_in[27];
    const float* het_b2   = (const float*)d_in[28];

    float* out_hcf = (float*)d_out;
    float* out_hc  = out_hcf + (size_t)NN * D;
    float* out_hs  = out_hcf + (size_t)2 * NN * D;

    cudaFuncSetAttribute(tc_gemm<0>, cudaFuncAttributeMaxDynamicSharedMemorySize, SMEM_BYTES);
    cudaFuncSetAttribute(tc_gemm<1>, cudaFuncAttributeMaxDynamicSharedMemorySize, SMEM_BYTES);

    const int ZB = 256, ZG = 2048;
    const int sgrid = EH / 8;
    const int tgrid = (NN + 127) / 128;   // 782

    prep_weights<<<28, 128>>>(gcn_W1, gcn_W2, rg_W1, rg_loop1, rg_W2, rg_loop2,
                              het_W1, het_W2);

    // ---- GCN branch ----
    zero_kernel<<<ZG, ZB>>>(2, NN * 32);
    scatter_kernel<<<sgrid, 256>>>(0, emb, gcn_src1, gcn_dst1, nullptr, 0, 1, 2, EH);
    tc_gemm<0><<<tgrid, 512, SMEM_BYTES>>>(2, nullptr, 1, 0, 0, nullptr, -1, gcn_b1, nullptr, 1);
    zero_kernel<<<ZG, ZB>>>(2, NN * 32);
    scatter_kernel<<<sgrid, 256>>>(1, nullptr, gcn_src2, gcn_dst2, nullptr, 0, 1, 2, EH);
    tc_gemm<0><<<tgrid, 512, SMEM_BYTES>>>(2, nullptr, 1, 1, 0, nullptr, -1, gcn_b2, out_hcf, 0);

    // ---- RGCN branch ----
    zero_kernel<<<ZG, ZB>>>(3, NN * RRG * 32);
    scatter_kernel<<<sgrid, 256>>>(0, emb, rg_src1, rg_dst1, rg_et1, 0, RRG, 3, EH);
    tc_gemm<0><<<tgrid, 512, SMEM_BYTES>>>(3, nullptr, RRG, 2, 0, emb, 10, rg_b1, nullptr, 1);
    zero_kernel<<<ZG, ZB>>>(3, NN * RRG * 32);
    scatter_kernel<<<sgrid, 256>>>(1, nullptr, rg_src2, rg_dst2, rg_et2, 0, RRG, 3, EH);
    tc_gemm<0><<<tgrid, 512, SMEM_BYTES>>>(3, nullptr, RRG, 11, 1, nullptr, 19, rg_b2, out_hc, 0);

    // ---- Hetero branch ----
    zero_kernel<<<ZG, ZB>>>(4, NN * RHET * 32);
    scatter_kernel<<<sgrid, 256>>>(0, emb, het_src1, het_dst1, nullptr, EREL, RHET, 4, EH);
    tc_gemm<1><<<tgrid, 512, SMEM_BYTES>>>(4, nullptr, RHET, 20, 0, nullptr, -1, het_b1, nullptr, 1);
    zero_kernel<<<ZG, ZB>>>(4, NN * RHET * 32);
    scatter_kernel<<<sgrid, 256>>>(1, nullptr, het_src2, het_dst2, nullptr, EREL, RHET, 4, EH);
    tc_gemm<1><<<tgrid, 512, SMEM_BYTES>>>(4, nullptr, RHET, 24, 0, nullptr, -1, het_b2, out_hs, 0);
}

// round 7
// speedup vs baseline: 1.7703x; 1.0429x over previous
#include <cuda_runtime.h>
#include <cuda_bf16.h>
#include <cstdint>

#define NN   100000
#define D    128
#define EH   600000
#define RRG  8
#define RHET 4
#define EREL 150000

// ---- scratch (device globals: no cudaMalloc allowed) ----
__device__ float g_h  [NN * D];                     // 51.2 MB
__device__ float g_agg[NN * D];                     // 51.2 MB
__device__ float g_rb [(size_t)NN * RRG * D];       // 409.6 MB
__device__ float g_hb [(size_t)NN * RHET * D];      // 204.8 MB
// 28 weight matrices, each: bf16 hi block [128k][144] then lo block, 73728 B
#define WSTRIDE 73728
__device__ unsigned char g_wprep[28 * WSTRIDE];

__device__ __forceinline__ float* selbuf(int w, float* dflt) {
    switch (w) {
        case 1: return g_h;
        case 2: return g_agg;
        case 3: return g_rb;
        case 4: return g_hb;
        default: return dflt;
    }
}

// ============================ PTX helpers ==================================
__device__ __forceinline__ uint32_t smem_u32(const void* p) {
    uint32_t a;
    asm("{ .reg .u64 t; cvta.to.shared.u64 t, %1; cvt.u32.u64 %0, t; }" : "=r"(a) : "l"(p));
    return a;
}
__device__ __forceinline__ void ldsm4(uint32_t a, uint32_t* r) {
    asm volatile("ldmatrix.sync.aligned.m8n8.x4.shared.b16 {%0,%1,%2,%3}, [%4];"
                 : "=r"(r[0]), "=r"(r[1]), "=r"(r[2]), "=r"(r[3]) : "r"(a));
}
__device__ __forceinline__ void ldsm4t(uint32_t a, uint32_t* r) {
    asm volatile("ldmatrix.sync.aligned.m8n8.x4.trans.shared.b16 {%0,%1,%2,%3}, [%4];"
                 : "=r"(r[0]), "=r"(r[1]), "=r"(r[2]), "=r"(r[3]) : "r"(a));
}
__device__ __forceinline__ void mma_bf16(float* d, const uint32_t* a, const uint32_t* b) {
    asm volatile(
        "mma.sync.aligned.m16n8k16.row.col.f32.bf16.bf16.f32 "
        "{%0,%1,%2,%3}, {%4,%5,%6,%7}, {%8,%9}, {%0,%1,%2,%3};"
        : "+f"(d[0]), "+f"(d[1]), "+f"(d[2]), "+f"(d[3])
        : "r"(a[0]), "r"(a[1]), "r"(a[2]), "r"(a[3]), "r"(b[0]), "r"(b[1]));
}
__device__ __forceinline__ uint32_t pk_bf16x2(float lo, float hi) {
    uint32_t r;
    asm("cvt.rn.bf16x2.f32 %0, %1, %2;" : "=r"(r) : "f"(hi), "f"(lo));
    return r;
}
__device__ __forceinline__ float bfbits2f(uint32_t b16) { return __uint_as_float(b16 << 16); }
__device__ __forceinline__ void cp_async16(uint32_t saddr, const void* gaddr) {
    asm volatile("cp.async.ca.shared.global [%0], [%1], 16;"
                 :: "r"(saddr), "l"(gaddr) : "memory");
}
__device__ __forceinline__ void cp_commit() {
    asm volatile("cp.async.commit_group;" ::: "memory");
}
__device__ __forceinline__ void cp_wait0() {
    asm volatile("cp.async.wait_group 0;" ::: "memory");
}

// ============================ simple kernels ===============================
__global__ void __launch_bounds__(256) zero_kernel(int which, int n4) {
    float4* p = (float4*)selbuf(which, nullptr);
    int i = blockIdx.x * blockDim.x + threadIdx.x;
    int stride = gridDim.x * blockDim.x;
    float4 z = make_float4(0.f, 0.f, 0.f, 0.f);
    for (; i < n4; i += stride) p[i] = z;
}

__global__ void __launch_bounds__(256) scatter_kernel(
        int xWhich, const float* xExt,
        const int* __restrict__ src, const int* __restrict__ dst,
        const int* __restrict__ et, int relDiv,
        int outR, int outWhich, int E) {
    int gw = (blockIdx.x * blockDim.x + threadIdx.x) >> 5;
    if (gw >= E) return;
    int lane = threadIdx.x & 31;
    const float4* x = (const float4*)selbuf(xWhich, (float*)xExt);
    float4* out = (float4*)selbuf(outWhich, nullptr);
    int s = src[gw];
    int d = dst[gw];
    int r = et ? et[gw] : (relDiv ? (gw / relDiv) : 0);
    size_t dIdx = (size_t)d * outR + (outR > 1 ? r : 0);
    float4 v = x[(size_t)s * 32 + lane];
    float4* o = out + dIdx * 32 + lane;
    asm volatile("red.global.add.v4.f32 [%0], {%1,%2,%3,%4};"
                 :: "l"(o), "f"(v.x), "f"(v.y), "f"(v.z), "f"(v.w)
                 : "memory");
}

// ============================ weight prep ==================================
// For each of 28 fp32 [128k x 128c] matrices: split into bf16 hi/lo, stored
// row-major [k][c] with row stride 144 elements (288 B, conflict-free ldmatrix).
__global__ void __launch_bounds__(128) prep_weights(
        const float* gcn_W1, const float* gcn_W2,
        const float* rg_W1, const float* rg_loop1,
        const float* rg_W2, const float* rg_loop2,
        const float* het_W1, const float* het_W2) {
    int blk = blockIdx.x;
    const float* W;
    if      (blk == 0)  W = gcn_W1;
    else if (blk == 1)  W = gcn_W2;
    else if (blk < 10)  W = rg_W1 + (size_t)(blk - 2) * 16384;
    else if (blk == 10) W = rg_loop1;
    else if (blk < 19)  W = rg_W2 + (size_t)(blk - 11) * 16384;
    else if (blk == 19) W = rg_loop2;
    else if (blk < 24)  W = het_W1 + (size_t)(blk - 20) * 16384;
    else                W = het_W2 + (size_t)(blk - 24) * 16384;

    __nv_bfloat16* dh = (__nv_bfloat16*)(g_wprep + (size_t)blk * WSTRIDE);
    __nv_bfloat16* dl = dh + 128 * 144;
    int c = threadIdx.x;
    for (int k = 0; k < 128; k++) {
        float w = W[k * 128 + c];
        __nv_bfloat16 h = __float2bfloat16(w);
        __nv_bfloat16 l = __float2bfloat16(w - __bfloat162float(h));
        dh[k * 144 + c] = h;
        dl[k * 144 + c] = l;
    }
}

// ============================ HMMA GEMM ====================================
// 256 threads, 8 warps, CTA tile 64 rows x 128 cols (2 CTAs/SM for overlap).
// K accumulated over nChunks (+ optional self-loop chunk). 3-term bf16 split,
// fp32 register acc. Warp (wr = wid&3, wc = wid>>2): rows wr*16, cols wc*64.
//   PCT=0: out = tanh(sum_ch A_ch @ W_ch (+ X@Wl) + b)
//   PCT=1: out = (1/nChunks) * sum_ch tanh(A_ch @ W_ch + b_ch)
#define SM_AH 0
#define SM_AL 18432
#define SM_WH 36864
#define SM_WL 73728
#define SMEM_BYTES 110592

template <int PCT>
__global__ void __launch_bounds__(256) tc_gemm(
        int aWhich, const float* aExt, int nChunks, int wBase,
        int xWhich, const float* xExt, int xWIdx,
        const float* __restrict__ b,
        float* outExt, int outWhich) {
    extern __shared__ unsigned char smem[];
    uint32_t sb = smem_u32(smem);
    int t = threadIdx.x, wid = t >> 5, lane = t & 31;
    int wr = wid & 3, wc = wid >> 2;
    int n0 = blockIdx.x * 64;

    const float* A = selbuf(aWhich, (float*)aExt);
    const float* X = (xWIdx >= 0) ? selbuf(xWhich, (float*)xExt) : nullptr;
    float* out = selbuf(outWhich, outExt);

    float acc[8][4];
    float fin[8][4];
#pragma unroll
    for (int i = 0; i < 8; i++)
#pragma unroll
        for (int j = 0; j < 4; j++) { acc[i][j] = 0.f; fin[i][j] = 0.f; }

    int ldA = nChunks * 128;
    int tot = nChunks + (X ? 1 : 0);

    // per-lane ldmatrix address pieces (bytes); row stride 288
    uint32_t lmrow = (uint32_t)(lane & 15) * 288 + (uint32_t)(lane >> 4) * 16;
    uint32_t aAddrBase = sb + (uint32_t)wr * 4608 + lmrow;   // + (AH|AL) + ks*32
    uint32_t bAddrBase = sb + lmrow + (uint32_t)wc * 128;    // + (WH|WL) + ks*4608 + g*32

    for (int ch = 0; ch < tot; ch++) {
        const float* Asrc; int ld, kOff, wIdx;
        if (ch < nChunks) { Asrc = A; ld = ldA; kOff = ch * 128; wIdx = wBase + ch; }
        else              { Asrc = X; ld = 128; kOff = 0;        wIdx = xWIdx; }

        __syncthreads();
        // ---- async copy pre-split W image (hi+lo, 73728 B = 4608 x 16B) ----
        {
            const uint4* ws = (const uint4*)(g_wprep + (size_t)wIdx * WSTRIDE);
#pragma unroll 18
            for (int i = t; i < 4608; i += 256)
                cp_async16(sb + SM_WH + (uint32_t)i * 16, ws + i);
            cp_commit();
        }
        // ---- stage A: fp32 -> bf16 hi/lo, padded rows (overlaps cp.async) ----
#pragma unroll
        for (int i = 0; i < 8; i++) {
            int f = t + i * 256;
            int row = f >> 5, c4 = f & 31;
            int rc = n0 + row; if (rc > NN - 1) rc = NN - 1;
            float4 v = *(const float4*)(Asrc + (size_t)rc * ld + kOff + c4 * 4);
            uint32_t h01 = pk_bf16x2(v.x, v.y);
            uint32_t h23 = pk_bf16x2(v.z, v.w);
            uint32_t l01 = pk_bf16x2(v.x - bfbits2f(h01 & 0xFFFFu),
                                     v.y - bfbits2f(h01 >> 16));
            uint32_t l23 = pk_bf16x2(v.z - bfbits2f(h23 & 0xFFFFu),
                                     v.w - bfbits2f(h23 >> 16));
            uint32_t off = (uint32_t)row * 288 + (uint32_t)c4 * 8;
            *(uint2*)(smem + SM_AH + off) = make_uint2(h01, h23);
            *(uint2*)(smem + SM_AL + off) = make_uint2(l01, l23);
        }
        cp_wait0();
        __syncthreads();

        // ---- compute: 3-term bf16 split ----
#pragma unroll
        for (int ks = 0; ks < 8; ks++) {
            uint32_t ah[4], al[4];
            ldsm4(aAddrBase + SM_AH + ks * 32, ah);
            ldsm4(aAddrBase + SM_AL + ks * 32, al);
#pragma unroll
            for (int g = 0; g < 4; g++) {
                uint32_t bh[4], bl[4];
                uint32_t baddr = bAddrBase + (uint32_t)ks * 4608 + (uint32_t)g * 32;
                ldsm4t(baddr + SM_WH, bh);
                ldsm4t(baddr + SM_WL, bl);
                mma_bf16(acc[g * 2],     ah, bh);
                mma_bf16(acc[g * 2 + 1], ah, bh + 2);
                mma_bf16(acc[g * 2],     al, bh);
                mma_bf16(acc[g * 2 + 1], al, bh + 2);
                mma_bf16(acc[g * 2],     ah, bl);
                mma_bf16(acc[g * 2 + 1], ah, bl + 2);
            }
        }

        if (PCT) {
#pragma unroll
            for (int nt = 0; nt < 8; nt++) {
                int col = wc * 64 + nt * 8 + (lane & 3) * 2;
                float2 bb = *(const float2*)(b + ch * 128 + col);
                fin[nt][0] += tanhf(acc[nt][0] + bb.x);
                fin[nt][1] += tanhf(acc[nt][1] + bb.y);
                fin[nt][2] += tanhf(acc[nt][2] + bb.x);
                fin[nt][3] += tanhf(acc[nt][3] + bb.y);
                acc[nt][0] = acc[nt][1] = acc[nt][2] = acc[nt][3] = 0.f;
            }
        }
    }

    // ---- epilogue ----
    int r0 = n0 + wr * 16 + (lane >> 2);
    int r1 = r0 + 8;
    if (!PCT) {
#pragma unroll
        for (int nt = 0; nt < 8; nt++) {
            int col = wc * 64 + nt * 8 + (lane & 3) * 2;
            float2 bb = *(const float2*)(b + col);
            if (r0 < NN) {
                float2 o = make_float2(tanhf(acc[nt][0] + bb.x), tanhf(acc[nt][1] + bb.y));
                *(float2*)(out + (size_t)r0 * 128 + col) = o;
            }
            if (r1 < NN) {
                float2 o = make_float2(tanhf(acc[nt][2] + bb.x), tanhf(acc[nt][3] + bb.y));
                *(float2*)(out + (size_t)r1 * 128 + col) = o;
            }
        }
    } else {
        float s = 1.0f / (float)nChunks;
#pragma unroll
        for (int nt = 0; nt < 8; nt++) {
            int col = wc * 64 + nt * 8 + (lane & 3) * 2;
            if (r0 < NN) {
                float2 o = make_float2(fin[nt][0] * s, fin[nt][1] * s);
                *(float2*)(out + (size_t)r0 * 128 + col) = o;
            }
            if (r1 < NN) {
                float2 o = make_float2(fin[nt][2] * s, fin[nt][3] * s);
                *(float2*)(out + (size_t)r1 * 128 + col) = o;
            }
        }
    }
}

// ---------------------------------------------------------------------------
extern "C" void kernel_launch(void* const* d_in, const int* in_sizes, int n_in,
                              void* d_out, int out_size) {
    const int*   gcn_src1 = (const int*)d_in[0];
    const int*   gcn_dst1 = (const int*)d_in[1];
    const int*   gcn_src2 = (const int*)d_in[2];
    const int*   gcn_dst2 = (const int*)d_in[3];
    const int*   rg_src1  = (const int*)d_in[4];
    const int*   rg_dst1  = (const int*)d_in[5];
    const int*   rg_et1   = (const int*)d_in[6];
    const int*   rg_src2  = (const int*)d_in[7];
    const int*   rg_dst2  = (const int*)d_in[8];
    const int*   rg_et2   = (const int*)d_in[9];
    const int*   het_src1 = (const int*)d_in[10];
    const int*   het_dst1 = (const int*)d_in[11];
    const int*   het_src2 = (const int*)d_in[12];
    const int*   het_dst2 = (const int*)d_in[13];
    const float* emb      = (const float*)d_in[14];
    const float* gcn_W1   = (const float*)d_in[15];
    const float* gcn_b1   = (const float*)d_in[16];
    const float* gcn_W2   = (const float*)d_in[17];
    const float* gcn_b2   = (const float*)d_in[18];
    const float* rg_W1    = (const float*)d_in[19];
    const float* rg_loop1 = (const float*)d_in[20];
    const float* rg_b1    = (const float*)d_in[21];
    const float* rg_W2    = (const float*)d_in[22];
    const float* rg_loop2 = (const float*)d_in[23];
    const float* rg_b2    = (const float*)d_in[24];
    const float* het_W1   = (const float*)d_in[25];
    const float* het_b1   = (const float*)d_in[26];
    const float* het_W2   = (const float*)d_in[27];
    const float* het_b2   = (const float*)d_in[28];

    float* out_hcf = (float*)d_out;
    float* out_hc  = out_hcf + (size_t)NN * D;
    float* out_hs  = out_hcf + (size_t)2 * NN * D;

    cudaFuncSetAttribute(tc_gemm<0>, cudaFuncAttributeMaxDynamicSharedMemorySize, SMEM_BYTES);
    cudaFuncSetAttribute(tc_gemm<1>, cudaFuncAttributeMaxDynamicSharedMemorySize, SMEM_BYTES);

    const int ZB = 256, ZG = 2048;
    const int sgrid = EH / 8;
    const int tgrid = (NN + 63) / 64;   // 1563

    prep_weights<<<28, 128>>>(gcn_W1, gcn_W2, rg_W1, rg_loop1, rg_W2, rg_loop2,
                              het_W1, het_W2);

    // ---- GCN branch ----
    zero_kernel<<<ZG, ZB>>>(2, NN * 32);
    scatter_kernel<<<sgrid, 256>>>(0, emb, gcn_src1, gcn_dst1, nullptr, 0, 1, 2, EH);
    tc_gemm<0><<<tgrid, 256, SMEM_BYTES>>>(2, nullptr, 1, 0, 0, nullptr, -1, gcn_b1, nullptr, 1);
    zero_kernel<<<ZG, ZB>>>(2, NN * 32);
    scatter_kernel<<<sgrid, 256>>>(1, nullptr, gcn_src2, gcn_dst2, nullptr, 0, 1, 2, EH);
    tc_gemm<0><<<tgrid, 256, SMEM_BYTES>>>(2, nullptr, 1, 1, 0, nullptr, -1, gcn_b2, out_hcf, 0);

    // ---- RGCN branch ----
    zero_kernel<<<ZG, ZB>>>(3, NN * RRG * 32);
    scatter_kernel<<<sgrid, 256>>>(0, emb, rg_src1, rg_dst1, rg_et1, 0, RRG, 3, EH);
    tc_gemm<0><<<tgrid, 256, SMEM_BYTES>>>(3, nullptr, RRG, 2, 0, emb, 10, rg_b1, nullptr, 1);
    zero_kernel<<<ZG, ZB>>>(3, NN * RRG * 32);
    scatter_kernel<<<sgrid, 256>>>(1, nullptr, rg_src2, rg_dst2, rg_et2, 0, RRG, 3, EH);
    tc_gemm<0><<<tgrid, 256, SMEM_BYTES>>>(3, nullptr, RRG, 11, 1, nullptr, 19, rg_b2, out_hc, 0);

    // ---- Hetero branch ----
    zero_kernel<<<ZG, ZB>>>(4, NN * RHET * 32);
    scatter_kernel<<<sgrid, 256>>>(0, emb, het_src1, het_dst1, nullptr, EREL, RHET, 4, EH);
    tc_gemm<1><<<tgrid, 256, SMEM_BYTES>>>(4, nullptr, RHET, 20, 0, nullptr, -1, het_b1, nullptr, 1);
    zero_kernel<<<ZG, ZB>>>(4, NN * RHET * 32);
    scatter_kernel<<<sgrid, 256>>>(1, nullptr, het_src2, het_dst2, nullptr, EREL, RHET, 4, EH);
    tc_gemm<1><<<tgrid, 256, SMEM_BYTES>>>(4, nullptr, RHET, 24, 0, nullptr, -1, het_b2, out_hs, 0);
}

// round 8
// speedup vs baseline: 1.8058x; 1.0201x over previous
#include <cuda_runtime.h>
#include <cuda_bf16.h>
#include <cstdint>

#define NN   100000
#define D    128
#define EH   600000
#define RRG  8
#define RHET 4
#define EREL 150000

// ---- scratch (device globals: no cudaMalloc allowed) ----
__device__ float g_h  [NN * D];                     // 51.2 MB
__device__ float g_agg[NN * D];                     // 51.2 MB
__device__ float g_rb [(size_t)NN * RRG * D];       // 409.6 MB
__device__ float g_hb [(size_t)NN * RHET * D];      // 204.8 MB
// 28 weight matrices, each: bf16 hi block [128k][144] then lo block, 73728 B
#define WSTRIDE 73728
__device__ unsigned char g_wprep[28 * WSTRIDE];

__device__ __forceinline__ float* selbuf(int w, float* dflt) {
    switch (w) {
        case 1: return g_h;
        case 2: return g_agg;
        case 3: return g_rb;
        case 4: return g_hb;
        default: return dflt;
    }
}

// ============================ PTX helpers ==================================
__device__ __forceinline__ uint32_t smem_u32(const void* p) {
    uint32_t a;
    asm("{ .reg .u64 t; cvta.to.shared.u64 t, %1; cvt.u32.u64 %0, t; }" : "=r"(a) : "l"(p));
    return a;
}
__device__ __forceinline__ void ldsm4(uint32_t a, uint32_t* r) {
    asm volatile("ldmatrix.sync.aligned.m8n8.x4.shared.b16 {%0,%1,%2,%3}, [%4];"
                 : "=r"(r[0]), "=r"(r[1]), "=r"(r[2]), "=r"(r[3]) : "r"(a));
}
__device__ __forceinline__ void ldsm4t(uint32_t a, uint32_t* r) {
    asm volatile("ldmatrix.sync.aligned.m8n8.x4.trans.shared.b16 {%0,%1,%2,%3}, [%4];"
                 : "=r"(r[0]), "=r"(r[1]), "=r"(r[2]), "=r"(r[3]) : "r"(a));
}
__device__ __forceinline__ void mma_bf16(float* d, const uint32_t* a, const uint32_t* b) {
    asm volatile(
        "mma.sync.aligned.m16n8k16.row.col.f32.bf16.bf16.f32 "
        "{%0,%1,%2,%3}, {%4,%5,%6,%7}, {%8,%9}, {%0,%1,%2,%3};"
        : "+f"(d[0]), "+f"(d[1]), "+f"(d[2]), "+f"(d[3])
        : "r"(a[0]), "r"(a[1]), "r"(a[2]), "r"(a[3]), "r"(b[0]), "r"(b[1]));
}
__device__ __forceinline__ uint32_t pk_bf16x2(float lo, float hi) {
    uint32_t r;
    asm("cvt.rn.bf16x2.f32 %0, %1, %2;" : "=r"(r) : "f"(hi), "f"(lo));
    return r;
}
__device__ __forceinline__ float bfbits2f(uint32_t b16) { return __uint_as_float(b16 << 16); }
__device__ __forceinline__ void cp_async16(uint32_t saddr, const void* gaddr) {
    asm volatile("cp.async.ca.shared.global [%0], [%1], 16;"
                 :: "r"(saddr), "l"(gaddr) : "memory");
}
__device__ __forceinline__ void cp_commit() {
    asm volatile("cp.async.commit_group;" ::: "memory");
}
__device__ __forceinline__ void cp_wait0() {
    asm volatile("cp.async.wait_group 0;" ::: "memory");
}

// ============================ simple kernels ===============================
__global__ void __launch_bounds__(256) zero_kernel(int which, int n4) {
    float4* p = (float4*)selbuf(which, nullptr);
    int i = blockIdx.x * blockDim.x + threadIdx.x;
    int stride = gridDim.x * blockDim.x;
    float4 z = make_float4(0.f, 0.f, 0.f, 0.f);
    for (; i < n4; i += stride) p[i] = z;
}

__global__ void __launch_bounds__(256) scatter_kernel(
        int xWhich, const float* xExt,
        const int* __restrict__ src, const int* __restrict__ dst,
        const int* __restrict__ et, int relDiv,
        int outR, int outWhich, int E) {
    int gw = (blockIdx.x * blockDim.x + threadIdx.x) >> 5;
    if (gw >= E) return;
    int lane = threadIdx.x & 31;
    const float4* x = (const float4*)selbuf(xWhich, (float*)xExt);
    float4* out = (float4*)selbuf(outWhich, nullptr);
    int s = src[gw];
    int d = dst[gw];
    int r = et ? et[gw] : (relDiv ? (gw / relDiv) : 0);
    size_t dIdx = (size_t)d * outR + (outR > 1 ? r : 0);
    float4 v = x[(size_t)s * 32 + lane];
    float4* o = out + dIdx * 32 + lane;
    asm volatile("red.global.add.v4.f32 [%0], {%1,%2,%3,%4};"
                 :: "l"(o), "f"(v.x), "f"(v.y), "f"(v.z), "f"(v.w)
                 : "memory");
}

// ============================ weight prep ==================================
// For each of 28 fp32 [128k x 128c] matrices: split into bf16 hi/lo, stored
// row-major [k][c] with row stride 144 elements (288 B, conflict-free ldmatrix).
__global__ void __launch_bounds__(128) prep_weights(
        const float* gcn_W1, const float* gcn_W2,
        const float* rg_W1, const float* rg_loop1,
        const float* rg_W2, const float* rg_loop2,
        const float* het_W1, const float* het_W2) {
    int blk = blockIdx.x;
    const float* W;
    if      (blk == 0)  W = gcn_W1;
    else if (blk == 1)  W = gcn_W2;
    else if (blk < 10)  W = rg_W1 + (size_t)(blk - 2) * 16384;
    else if (blk == 10) W = rg_loop1;
    else if (blk < 19)  W = rg_W2 + (size_t)(blk - 11) * 16384;
    else if (blk == 19) W = rg_loop2;
    else if (blk < 24)  W = het_W1 + (size_t)(blk - 20) * 16384;
    else                W = het_W2 + (size_t)(blk - 24) * 16384;

    __nv_bfloat16* dh = (__nv_bfloat16*)(g_wprep + (size_t)blk * WSTRIDE);
    __nv_bfloat16* dl = dh + 128 * 144;
    int c = threadIdx.x;
    for (int k = 0; k < 128; k++) {
        float w = W[k * 128 + c];
        __nv_bfloat16 h = __float2bfloat16(w);
        __nv_bfloat16 l = __float2bfloat16(w - __bfloat162float(h));
        dh[k * 144 + c] = h;
        dl[k * 144 + c] = l;
    }
}

// ============================ HMMA GEMM ====================================
// 256 threads, 8 warps, CTA tile 64 rows x 128 cols.
// Two-phase W: a single 36 KB W buffer holds WH for phase 1 (ah*bh + al*bh)
// then WL for phase 2 (ah*bl). smem/CTA = 72 KB -> 3 CTAs/SM (24 warps).
//   PCT=0: out = tanh(sum_ch A_ch @ W_ch (+ X@Wl) + b)
//   PCT=1: out = (1/nChunks) * sum_ch tanh(A_ch @ W_ch + b_ch)
#define SM_AH 0
#define SM_AL 18432
#define SM_W  36864
#define SMEM_BYTES 73728

template <int PCT>
__global__ void __launch_bounds__(256, 3) tc_gemm(
        int aWhich, const float* aExt, int nChunks, int wBase,
        int xWhich, const float* xExt, int xWIdx,
        const float* __restrict__ b,
        float* outExt, int outWhich) {
    extern __shared__ unsigned char smem[];
    uint32_t sb = smem_u32(smem);
    int t = threadIdx.x, wid = t >> 5, lane = t & 31;
    int wr = wid & 3, wc = wid >> 2;
    int n0 = blockIdx.x * 64;

    const float* A = selbuf(aWhich, (float*)aExt);
    const float* X = (xWIdx >= 0) ? selbuf(xWhich, (float*)xExt) : nullptr;
    float* out = selbuf(outWhich, outExt);

    float acc[8][4];
    float fin[8][4];
#pragma unroll
    for (int i = 0; i < 8; i++)
#pragma unroll
        for (int j = 0; j < 4; j++) { acc[i][j] = 0.f; fin[i][j] = 0.f; }

    int ldA = nChunks * 128;
    int tot = nChunks + (X ? 1 : 0);

    // per-lane ldmatrix address pieces (bytes); row stride 288
    uint32_t lmrow = (uint32_t)(lane & 15) * 288 + (uint32_t)(lane >> 4) * 16;
    uint32_t aAddrBase = sb + (uint32_t)wr * 4608 + lmrow;   // + (AH|AL) + ks*32
    uint32_t bAddrBase = sb + SM_W + lmrow + (uint32_t)wc * 128; // + ks*4608 + g*32

    for (int ch = 0; ch < tot; ch++) {
        const float* Asrc; int ld, kOff, wIdx;
        if (ch < nChunks) { Asrc = A; ld = ldA; kOff = ch * 128; wIdx = wBase + ch; }
        else              { Asrc = X; ld = 128; kOff = 0;        wIdx = xWIdx; }

        const unsigned char* wimg = g_wprep + (size_t)wIdx * WSTRIDE;

        __syncthreads();   // W & A buffers free (prev chunk phase 2 done)
        // ---- async copy WH (36864 B = 2304 x 16B) ----
#pragma unroll 9
        for (int i = t; i < 2304; i += 256)
            cp_async16(sb + SM_W + (uint32_t)i * 16, wimg + (size_t)i * 16);
        cp_commit();
        // ---- stage A: fp32 -> bf16 hi/lo, padded rows (overlaps cp.async) ----
#pragma unroll
        for (int i = 0; i < 8; i++) {
            int f = t + i * 256;
            int row = f >> 5, c4 = f & 31;
            int rc = n0 + row; if (rc > NN - 1) rc = NN - 1;
            float4 v = *(const float4*)(Asrc + (size_t)rc * ld + kOff + c4 * 4);
            uint32_t h01 = pk_bf16x2(v.x, v.y);
            uint32_t h23 = pk_bf16x2(v.z, v.w);
            uint32_t l01 = pk_bf16x2(v.x - bfbits2f(h01 & 0xFFFFu),
                                     v.y - bfbits2f(h01 >> 16));
            uint32_t l23 = pk_bf16x2(v.z - bfbits2f(h23 & 0xFFFFu),
                                     v.w - bfbits2f(h23 >> 16));
            uint32_t off = (uint32_t)row * 288 + (uint32_t)c4 * 8;
            *(uint2*)(smem + SM_AH + off) = make_uint2(h01, h23);
            *(uint2*)(smem + SM_AL + off) = make_uint2(l01, l23);
        }
        cp_wait0();
        __syncthreads();

        // ---- phase 1: ah*bh + al*bh ----
#pragma unroll
        for (int ks = 0; ks < 8; ks++) {
            uint32_t ah[4], al[4];
            ldsm4(aAddrBase + SM_AH + ks * 32, ah);
            ldsm4(aAddrBase + SM_AL + ks * 32, al);
#pragma unroll
            for (int g = 0; g < 4; g++) {
                uint32_t bh[4];
                ldsm4t(bAddrBase + (uint32_t)ks * 4608 + (uint32_t)g * 32, bh);
                mma_bf16(acc[g * 2],     ah, bh);
                mma_bf16(acc[g * 2 + 1], ah, bh + 2);
                mma_bf16(acc[g * 2],     al, bh);
                mma_bf16(acc[g * 2 + 1], al, bh + 2);
            }
        }
        __syncthreads();   // done reading WH
        // ---- async copy WL into same buffer ----
#pragma unroll 9
        for (int i = t; i < 2304; i += 256)
            cp_async16(sb + SM_W + (uint32_t)i * 16, wimg + 36864 + (size_t)i * 16);
        cp_commit();
        cp_wait0();
        __syncthreads();

        // ---- phase 2: ah*bl ----
#pragma unroll
        for (int ks = 0; ks < 8; ks++) {
            uint32_t ah[4];
            ldsm4(aAddrBase + SM_AH + ks * 32, ah);
#pragma unroll
            for (int g = 0; g < 4; g++) {
                uint32_t bl[4];
                ldsm4t(bAddrBase + (uint32_t)ks * 4608 + (uint32_t)g * 32, bl);
                mma_bf16(acc[g * 2],     ah, bl);
                mma_bf16(acc[g * 2 + 1], ah, bl + 2);
            }
        }

        if (PCT) {
#pragma unroll
            for (int nt = 0; nt < 8; nt++) {
                int col = wc * 64 + nt * 8 + (lane & 3) * 2;
                float2 bb = *(const float2*)(b + ch * 128 + col);
                fin[nt][0] += tanhf(acc[nt][0] + bb.x);
                fin[nt][1] += tanhf(acc[nt][1] + bb.y);
                fin[nt][2] += tanhf(acc[nt][2] + bb.x);
                fin[nt][3] += tanhf(acc[nt][3] + bb.y);
                acc[nt][0] = acc[nt][1] = acc[nt][2] = acc[nt][3] = 0.f;
            }
        }
    }

    // ---- epilogue ----
    int r0 = n0 + wr * 16 + (lane >> 2);
    int r1 = r0 + 8;
    if (!PCT) {
#pragma unroll
        for (int nt = 0; nt < 8; nt++) {
            int col = wc * 64 + nt * 8 + (lane & 3) * 2;
            float2 bb = *(const float2*)(b + col);
            if (r0 < NN) {
                float2 o = make_float2(tanhf(acc[nt][0] + bb.x), tanhf(acc[nt][1] + bb.y));
                *(float2*)(out + (size_t)r0 * 128 + col) = o;
            }
            if (r1 < NN) {
                float2 o = make_float2(tanhf(acc[nt][2] + bb.x), tanhf(acc[nt][3] + bb.y));
                *(float2*)(out + (size_t)r1 * 128 + col) = o;
            }
        }
    } else {
        float s = 1.0f / (float)nChunks;
#pragma unroll
        for (int nt = 0; nt < 8; nt++) {
            int col = wc * 64 + nt * 8 + (lane & 3) * 2;
            if (r0 < NN) {
                float2 o = make_float2(fin[nt][0] * s, fin[nt][1] * s);
                *(float2*)(out + (size_t)r0 * 128 + col) = o;
            }
            if (r1 < NN) {
                float2 o = make_float2(fin[nt][2] * s, fin[nt][3] * s);
                *(float2*)(out + (size_t)r1 * 128 + col) = o;
            }
        }
    }
}

// ---------------------------------------------------------------------------
extern "C" void kernel_launch(void* const* d_in, const int* in_sizes, int n_in,
                              void* d_out, int out_size) {
    const int*   gcn_src1 = (const int*)d_in[0];
    const int*   gcn_dst1 = (const int*)d_in[1];
    const int*   gcn_src2 = (const int*)d_in[2];
    const int*   gcn_dst2 = (const int*)d_in[3];
    const int*   rg_src1  = (const int*)d_in[4];
    const int*   rg_dst1  = (const int*)d_in[5];
    const int*   rg_et1   = (const int*)d_in[6];
    const int*   rg_src2  = (const int*)d_in[7];
    const int*   rg_dst2  = (const int*)d_in[8];
    const int*   rg_et2   = (const int*)d_in[9];
    const int*   het_src1 = (const int*)d_in[10];
    const int*   het_dst1 = (const int*)d_in[11];
    const int*   het_src2 = (const int*)d_in[12];
    const int*   het_dst2 = (const int*)d_in[13];
    const float* emb      = (const float*)d_in[14];
    const float* gcn_W1   = (const float*)d_in[15];
    const float* gcn_b1   = (const float*)d_in[16];
    const float* gcn_W2   = (const float*)d_in[17];
    const float* gcn_b2   = (const float*)d_in[18];
    const float* rg_W1    = (const float*)d_in[19];
    const float* rg_loop1 = (const float*)d_in[20];
    const float* rg_b1    = (const float*)d_in[21];
    const float* rg_W2    = (const float*)d_in[22];
    const float* rg_loop2 = (const float*)d_in[23];
    const float* rg_b2    = (const float*)d_in[24];
    const float* het_W1   = (const float*)d_in[25];
    const float* het_b1   = (const float*)d_in[26];
    const float* het_W2   = (const float*)d_in[27];
    const float* het_b2   = (const float*)d_in[28];

    float* out_hcf = (float*)d_out;
    float* out_hc  = out_hcf + (size_t)NN * D;
    float* out_hs  = out_hcf + (size_t)2 * NN * D;

    cudaFuncSetAttribute(tc_gemm<0>, cudaFuncAttributeMaxDynamicSharedMemorySize, SMEM_BYTES);
    cudaFuncSetAttribute(tc_gemm<1>, cudaFuncAttributeMaxDynamicSharedMemorySize, SMEM_BYTES);

    const int ZB = 256, ZG = 2048;
    const int sgrid = EH / 8;
    const int tgrid = (NN + 63) / 64;   // 1563

    prep_weights<<<28, 128>>>(gcn_W1, gcn_W2, rg_W1, rg_loop1, rg_W2, rg_loop2,
                              het_W1, het_W2);

    // ---- GCN branch ----
    zero_kernel<<<ZG, ZB>>>(2, NN * 32);
    scatter_kernel<<<sgrid, 256>>>(0, emb, gcn_src1, gcn_dst1, nullptr, 0, 1, 2, EH);
    tc_gemm<0><<<tgrid, 256, SMEM_BYTES>>>(2, nullptr, 1, 0, 0, nullptr, -1, gcn_b1, nullptr, 1);
    zero_kernel<<<ZG, ZB>>>(2, NN * 32);
    scatter_kernel<<<sgrid, 256>>>(1, nullptr, gcn_src2, gcn_dst2, nullptr, 0, 1, 2, EH);
    tc_gemm<0><<<tgrid, 256, SMEM_BYTES>>>(2, nullptr, 1, 1, 0, nullptr, -1, gcn_b2, out_hcf, 0);

    // ---- RGCN branch ----
    zero_kernel<<<ZG, ZB>>>(3, NN * RRG * 32);
    scatter_kernel<<<sgrid, 256>>>(0, emb, rg_src1, rg_dst1, rg_et1, 0, RRG, 3, EH);
    tc_gemm<0><<<tgrid, 256, SMEM_BYTES>>>(3, nullptr, RRG, 2, 0, emb, 10, rg_b1, nullptr, 1);
    zero_kernel<<<ZG, ZB>>>(3, NN * RRG * 32);
    scatter_kernel<<<sgrid, 256>>>(1, nullptr, rg_src2, rg_dst2, rg_et2, 0, RRG, 3, EH);
    tc_gemm<0><<<tgrid, 256, SMEM_BYTES>>>(3, nullptr, RRG, 11, 1, nullptr, 19, rg_b2, out_hc, 0);

    // ---- Hetero branch ----
    zero_kernel<<<ZG, ZB>>>(4, NN * RHET * 32);
    scatter_kernel<<<sgrid, 256>>>(0, emb, het_src1, het_dst1, nullptr, EREL, RHET, 4, EH);
    tc_gemm<1><<<tgrid, 256, SMEM_BYTES>>>(4, nullptr, RHET, 20, 0, nullptr, -1, het_b1, nullptr, 1);
    zero_kernel<<<ZG, ZB>>>(4, NN * RHET * 32);
    scatter_kernel<<<sgrid, 256>>>(1, nullptr, het_src2, het_dst2, nullptr, EREL, RHET, 4, EH);
    tc_gemm<1><<<tgrid, 256, SMEM_BYTES>>>(4, nullptr, RHET, 24, 0, nullptr, -1, het_b2, out_hs, 0);
}

// round 9
// speedup vs baseline: 1.9964x; 1.1055x over previous
#include <cuda_runtime.h>
#include <cuda_bf16.h>
#include <cstdint>

#define NN   100000
#define D    128
#define EH   600000
#define RRG  8
#define RHET 4
#define EREL 150000

// ---- scratch (device globals: no cudaMalloc allowed) ----
__device__ float g_h  [NN * D];                     // 51.2 MB
__device__ float g_agg[NN * D];                     // 51.2 MB
__device__ float g_rb [(size_t)NN * RRG * D];       // 409.6 MB
__device__ float g_hb [(size_t)NN * RHET * D];      // 204.8 MB
// 28 weight matrices, each: bf16 hi block [128k][144] then lo block, 73728 B
#define WSTRIDE 73728
__device__ unsigned char g_wprep[28 * WSTRIDE];

__device__ __forceinline__ float* selbuf(int w, float* dflt) {
    switch (w) {
        case 1: return g_h;
        case 2: return g_agg;
        case 3: return g_rb;
        case 4: return g_hb;
        default: return dflt;
    }
}

// ============================ PTX helpers ==================================
__device__ __forceinline__ uint32_t smem_u32(const void* p) {
    uint32_t a;
    asm("{ .reg .u64 t; cvta.to.shared.u64 t, %1; cvt.u32.u64 %0, t; }" : "=r"(a) : "l"(p));
    return a;
}
__device__ __forceinline__ void ldsm4(uint32_t a, uint32_t* r) {
    asm volatile("ldmatrix.sync.aligned.m8n8.x4.shared.b16 {%0,%1,%2,%3}, [%4];"
                 : "=r"(r[0]), "=r"(r[1]), "=r"(r[2]), "=r"(r[3]) : "r"(a));
}
__device__ __forceinline__ void ldsm4t(uint32_t a, uint32_t* r) {
    asm volatile("ldmatrix.sync.aligned.m8n8.x4.trans.shared.b16 {%0,%1,%2,%3}, [%4];"
                 : "=r"(r[0]), "=r"(r[1]), "=r"(r[2]), "=r"(r[3]) : "r"(a));
}
__device__ __forceinline__ void mma_bf16(float* d, const uint32_t* a, const uint32_t* b) {
    asm volatile(
        "mma.sync.aligned.m16n8k16.row.col.f32.bf16.bf16.f32 "
        "{%0,%1,%2,%3}, {%4,%5,%6,%7}, {%8,%9}, {%0,%1,%2,%3};"
        : "+f"(d[0]), "+f"(d[1]), "+f"(d[2]), "+f"(d[3])
        : "r"(a[0]), "r"(a[1]), "r"(a[2]), "r"(a[3]), "r"(b[0]), "r"(b[1]));
}
__device__ __forceinline__ uint32_t pk_bf16x2(float lo, float hi) {
    uint32_t r;
    asm("cvt.rn.bf16x2.f32 %0, %1, %2;" : "=r"(r) : "f"(hi), "f"(lo));
    return r;
}
__device__ __forceinline__ float bfbits2f(uint32_t b16) { return __uint_as_float(b16 << 16); }
__device__ __forceinline__ void cp_async16(uint32_t saddr, const void* gaddr) {
    asm volatile("cp.async.ca.shared.global [%0], [%1], 16;"
                 :: "r"(saddr), "l"(gaddr) : "memory");
}
__device__ __forceinline__ void cp_commit() {
    asm volatile("cp.async.commit_group;" ::: "memory");
}
__device__ __forceinline__ void cp_wait0() {
    asm volatile("cp.async.wait_group 0;" ::: "memory");
}

// ============================ simple kernels ===============================
__global__ void __launch_bounds__(256) zero_kernel(int which, int n4) {
    float4* p = (float4*)selbuf(which, nullptr);
    int i = blockIdx.x * blockDim.x + threadIdx.x;
    int stride = gridDim.x * blockDim.x;
    float4 z = make_float4(0.f, 0.f, 0.f, 0.f);
    for (; i < n4; i += stride) p[i] = z;
}

__global__ void __launch_bounds__(256) scatter_kernel(
        int xWhich, const float* xExt,
        const int* __restrict__ src, const int* __restrict__ dst,
        const int* __restrict__ et, int relDiv,
        int outR, int outWhich, int E) {
    int gw = (blockIdx.x * blockDim.x + threadIdx.x) >> 5;
    if (gw >= E) return;
    int lane = threadIdx.x & 31;
    const float4* x = (const float4*)selbuf(xWhich, (float*)xExt);
    float4* out = (float4*)selbuf(outWhich, nullptr);
    int s = src[gw];
    int d = dst[gw];
    int r = et ? et[gw] : (relDiv ? (gw / relDiv) : 0);
    size_t dIdx = (size_t)d * outR + (outR > 1 ? r : 0);
    float4 v = x[(size_t)s * 32 + lane];
    float4* o = out + dIdx * 32 + lane;
    asm volatile("red.global.add.v4.f32 [%0], {%1,%2,%3,%4};"
                 :: "l"(o), "f"(v.x), "f"(v.y), "f"(v.z), "f"(v.w)
                 : "memory");
}

// ============================ weight prep ==================================
__global__ void __launch_bounds__(128) prep_weights(
        const float* gcn_W1, const float* gcn_W2,
        const float* rg_W1, const float* rg_loop1,
        const float* rg_W2, const float* rg_loop2,
        const float* het_W1, const float* het_W2) {
    int blk = blockIdx.x;
    const float* W;
    if      (blk == 0)  W = gcn_W1;
    else if (blk == 1)  W = gcn_W2;
    else if (blk < 10)  W = rg_W1 + (size_t)(blk - 2) * 16384;
    else if (blk == 10) W = rg_loop1;
    else if (blk < 19)  W = rg_W2 + (size_t)(blk - 11) * 16384;
    else if (blk == 19) W = rg_loop2;
    else if (blk < 24)  W = het_W1 + (size_t)(blk - 20) * 16384;
    else                W = het_W2 + (size_t)(blk - 24) * 16384;

    __nv_bfloat16* dh = (__nv_bfloat16*)(g_wprep + (size_t)blk * WSTRIDE);
    __nv_bfloat16* dl = dh + 128 * 144;
    int c = threadIdx.x;
    for (int k = 0; k < 128; k++) {
        float w = W[k * 128 + c];
        __nv_bfloat16 h = __float2bfloat16(w);
        __nv_bfloat16 l = __float2bfloat16(w - __bfloat162float(h));
        dh[k * 144 + c] = h;
        dl[k * 144 + c] = l;
    }
}

// ==================== HMMA GEMM, M32 warps (PCT=0 path) ====================
// 256 threads, 8 warps, CTA tile 128 rows x 128 cols, warp tile 32x64
// (wr = wid&3 row group of 32 rows, wc = wid>>2 col group of 64).
// Two-phase W in one 36 KB buffer: phase1 WH (ah*bh + al*bh), phase2 WL (ah*bl).
// smem = A hi/lo 72 KB + W 36 KB = 108 KB -> 2 CTAs/SM.
// out = tanh(sum_ch A_ch @ W_ch (+ X@Wl) + b)
#define M32_AH 0
#define M32_AL 36864
#define M32_W  73728
#define SMEM_M32 110592

__global__ void __launch_bounds__(256, 2) tc_gemm32(
        int aWhich, const float* aExt, int nChunks, int wBase,
        int xWhich, const float* xExt, int xWIdx,
        const float* __restrict__ b,
        float* outExt, int outWhich) {
    extern __shared__ unsigned char smem[];
    uint32_t sb = smem_u32(smem);
    int t = threadIdx.x, wid = t >> 5, lane = t & 31;
    int wr = wid & 3, wc = wid >> 2;
    int n0 = blockIdx.x * 128;

    const float* A = selbuf(aWhich, (float*)aExt);
    const float* X = (xWIdx >= 0) ? selbuf(xWhich, (float*)xExt) : nullptr;
    float* out = selbuf(outWhich, outExt);

    float acc[2][8][4];
#pragma unroll
    for (int m = 0; m < 2; m++)
#pragma unroll
        for (int i = 0; i < 8; i++)
#pragma unroll
            for (int j = 0; j < 4; j++) acc[m][i][j] = 0.f;

    int ldA = nChunks * 128;
    int tot = nChunks + (X ? 1 : 0);

    // per-lane ldmatrix pieces (bytes); A/W row stride 288
    uint32_t lmrow = (uint32_t)(lane & 15) * 288 + (uint32_t)(lane >> 4) * 16;
    uint32_t aBase = sb + (uint32_t)wr * 9216 + lmrow;        // + AH|AL + m*4608 + ks*32
    uint32_t bBase = sb + M32_W + lmrow + (uint32_t)wc * 128; // + ks*4608 + g*32

    for (int ch = 0; ch < tot; ch++) {
        const float* Asrc; int ld, kOff, wIdx;
        if (ch < nChunks) { Asrc = A; ld = ldA; kOff = ch * 128; wIdx = wBase + ch; }
        else              { Asrc = X; ld = 128; kOff = 0;        wIdx = xWIdx; }

        const unsigned char* wimg = g_wprep + (size_t)wIdx * WSTRIDE;

        __syncthreads();
        // ---- async copy WH (36864 B) ----
#pragma unroll 9
        for (int i = t; i < 2304; i += 256)
            cp_async16(sb + M32_W + (uint32_t)i * 16, wimg + (size_t)i * 16);
        cp_commit();
        // ---- stage A (128 rows): fp32 -> bf16 hi/lo (overlaps cp.async) ----
#pragma unroll
        for (int i = 0; i < 16; i++) {
            int f = t + i * 256;
            int row = f >> 5, c4 = f & 31;
            int rc = n0 + row; if (rc > NN - 1) rc = NN - 1;
            float4 v = *(const float4*)(Asrc + (size_t)rc * ld + kOff + c4 * 4);
            uint32_t h01 = pk_bf16x2(v.x, v.y);
            uint32_t h23 = pk_bf16x2(v.z, v.w);
            uint32_t l01 = pk_bf16x2(v.x - bfbits2f(h01 & 0xFFFFu),
                                     v.y - bfbits2f(h01 >> 16));
            uint32_t l23 = pk_bf16x2(v.z - bfbits2f(h23 & 0xFFFFu),
                                     v.w - bfbits2f(h23 >> 16));
            uint32_t off = (uint32_t)row * 288 + (uint32_t)c4 * 8;
            *(uint2*)(smem + M32_AH + off) = make_uint2(h01, h23);
            *(uint2*)(smem + M32_AL + off) = make_uint2(l01, l23);
        }
        cp_wait0();
        __syncthreads();

        // ---- phase 1: ah*bh + al*bh (2 M-frags share each B fragment) ----
#pragma unroll
        for (int ks = 0; ks < 8; ks++) {
            uint32_t ah0[4], ah1[4], al0[4], al1[4];
            ldsm4(aBase + M32_AH + ks * 32, ah0);
            ldsm4(aBase + M32_AH + 4608 + ks * 32, ah1);
            ldsm4(aBase + M32_AL + ks * 32, al0);
            ldsm4(aBase + M32_AL + 4608 + ks * 32, al1);
#pragma unroll
            for (int g = 0; g < 4; g++) {
                uint32_t bh[4];
                ldsm4t(bBase + (uint32_t)ks * 4608 + (uint32_t)g * 32, bh);
                mma_bf16(acc[0][g * 2],     ah0, bh);
                mma_bf16(acc[0][g * 2 + 1], ah0, bh + 2);
                mma_bf16(acc[1][g * 2],     ah1, bh);
                mma_bf16(acc[1][g * 2 + 1], ah1, bh + 2);
                mma_bf16(acc[0][g * 2],     al0, bh);
                mma_bf16(acc[0][g * 2 + 1], al0, bh + 2);
                mma_bf16(acc[1][g * 2],     al1, bh);
                mma_bf16(acc[1][g * 2 + 1], al1, bh + 2);
            }
        }
        __syncthreads();   // done reading WH
        // ---- async copy WL into same buffer ----
#pragma unroll 9
        for (int i = t; i < 2304; i += 256)
            cp_async16(sb + M32_W + (uint32_t)i * 16, wimg + 36864 + (size_t)i * 16);
        cp_commit();
        cp_wait0();
        __syncthreads();

        // ---- phase 2: ah*bl ----
#pragma unroll
        for (int ks = 0; ks < 8; ks++) {
            uint32_t ah0[4], ah1[4];
            ldsm4(aBase + M32_AH + ks * 32, ah0);
            ldsm4(aBase + M32_AH + 4608 + ks * 32, ah1);
#pragma unroll
            for (int g = 0; g < 4; g++) {
                uint32_t bl[4];
                ldsm4t(bBase + (uint32_t)ks * 4608 + (uint32_t)g * 32, bl);
                mma_bf16(acc[0][g * 2],     ah0, bl);
                mma_bf16(acc[0][g * 2 + 1], ah0, bl + 2);
                mma_bf16(acc[1][g * 2],     ah1, bl);
                mma_bf16(acc[1][g * 2 + 1], ah1, bl + 2);
            }
        }
    }

    // ---- epilogue: bias + tanh + store ----
#pragma unroll
    for (int m = 0; m < 2; m++) {
        int r0 = n0 + wr * 32 + m * 16 + (lane >> 2);
        int r1 = r0 + 8;
#pragma unroll
        for (int nt = 0; nt < 8; nt++) {
            int col = wc * 64 + nt * 8 + (lane & 3) * 2;
            float2 bb = *(const float2*)(b + col);
            if (r0 < NN) {
                float2 o = make_float2(tanhf(acc[m][nt][0] + bb.x),
                                       tanhf(acc[m][nt][1] + bb.y));
                *(float2*)(out + (size_t)r0 * 128 + col) = o;
            }
            if (r1 < NN) {
                float2 o = make_float2(tanhf(acc[m][nt][2] + bb.x),
                                       tanhf(acc[m][nt][3] + bb.y));
                *(float2*)(out + (size_t)r1 * 128 + col) = o;
            }
        }
    }
}

// ==================== HMMA GEMM, M16 warps (hetero mean) ===================
// Round-8 kernel, PCT=1 semantics: out = (1/nChunks)*sum_ch tanh(A_ch@W_ch+b_ch)
#define SM_AH 0
#define SM_AL 18432
#define SM_W  36864
#define SMEM_BYTES 73728

__global__ void __launch_bounds__(256, 3) tc_gemm_mean(
        int aWhich, int nChunks, int wBase,
        const float* __restrict__ b,
        float* outExt, int outWhich) {
    extern __shared__ unsigned char smem[];
    uint32_t sb = smem_u32(smem);
    int t = threadIdx.x, wid = t >> 5, lane = t & 31;
    int wr = wid & 3, wc = wid >> 2;
    int n0 = blockIdx.x * 64;

    const float* A = selbuf(aWhich, nullptr);
    float* out = selbuf(outWhich, outExt);

    float acc[8][4];
    float fin[8][4];
#pragma unroll
    for (int i = 0; i < 8; i++)
#pragma unroll
        for (int j = 0; j < 4; j++) { acc[i][j] = 0.f; fin[i][j] = 0.f; }

    int ldA = nChunks * 128;

    uint32_t lmrow = (uint32_t)(lane & 15) * 288 + (uint32_t)(lane >> 4) * 16;
    uint32_t aAddrBase = sb + (uint32_t)wr * 4608 + lmrow;
    uint32_t bAddrBase = sb + SM_W + lmrow + (uint32_t)wc * 128;

    for (int ch = 0; ch < nChunks; ch++) {
        const unsigned char* wimg = g_wprep + (size_t)(wBase + ch) * WSTRIDE;

        __syncthreads();
#pragma unroll 9
        for (int i = t; i < 2304; i += 256)
            cp_async16(sb + SM_W + (uint32_t)i * 16, wimg + (size_t)i * 16);
        cp_commit();
#pragma unroll
        for (int i = 0; i < 8; i++) {
            int f = t + i * 256;
            int row = f >> 5, c4 = f & 31;
            int rc = n0 + row; if (rc > NN - 1) rc = NN - 1;
            float4 v = *(const float4*)(A + (size_t)rc * ldA + ch * 128 + c4 * 4);
            uint32_t h01 = pk_bf16x2(v.x, v.y);
            uint32_t h23 = pk_bf16x2(v.z, v.w);
            uint32_t l01 = pk_bf16x2(v.x - bfbits2f(h01 & 0xFFFFu),
                                     v.y - bfbits2f(h01 >> 16));
            uint32_t l23 = pk_bf16x2(v.z - bfbits2f(h23 & 0xFFFFu),
                                     v.w - bfbits2f(h23 >> 16));
            uint32_t off = (uint32_t)row * 288 + (uint32_t)c4 * 8;
            *(uint2*)(smem + SM_AH + off) = make_uint2(h01, h23);
            *(uint2*)(smem + SM_AL + off) = make_uint2(l01, l23);
        }
        cp_wait0();
        __syncthreads();

#pragma unroll
        for (int ks = 0; ks < 8; ks++) {
            uint32_t ah[4], al[4];
            ldsm4(aAddrBase + SM_AH + ks * 32, ah);
            ldsm4(aAddrBase + SM_AL + ks * 32, al);
#pragma unroll
            for (int g = 0; g < 4; g++) {
                uint32_t bh[4];
                ldsm4t(bAddrBase + (uint32_t)ks * 4608 + (uint32_t)g * 32, bh);
                mma_bf16(acc[g * 2],     ah, bh);
                mma_bf16(acc[g * 2 + 1], ah, bh + 2);
                mma_bf16(acc[g * 2],     al, bh);
                mma_bf16(acc[g * 2 + 1], al, bh + 2);
            }
        }
        __syncthreads();
#pragma unroll 9
        for (int i = t; i < 2304; i += 256)
            cp_async16(sb + SM_W + (uint32_t)i * 16, wimg + 36864 + (size_t)i * 16);
        cp_commit();
        cp_wait0();
        __syncthreads();

#pragma unroll
        for (int ks = 0; ks < 8; ks++) {
            uint32_t ah[4];
            ldsm4(aAddrBase + SM_AH + ks * 32, ah);
#pragma unroll
            for (int g = 0; g < 4; g++) {
                uint32_t bl[4];
                ldsm4t(bAddrBase + (uint32_t)ks * 4608 + (uint32_t)g * 32, bl);
                mma_bf16(acc[g * 2],     ah, bl);
                mma_bf16(acc[g * 2 + 1], ah, bl + 2);
            }
        }

#pragma unroll
        for (int nt = 0; nt < 8; nt++) {
            int col = wc * 64 + nt * 8 + (lane & 3) * 2;
            float2 bb = *(const float2*)(b + ch * 128 + col);
            fin[nt][0] += tanhf(acc[nt][0] + bb.x);
            fin[nt][1] += tanhf(acc[nt][1] + bb.y);
            fin[nt][2] += tanhf(acc[nt][2] + bb.x);
            fin[nt][3] += tanhf(acc[nt][3] + bb.y);
            acc[nt][0] = acc[nt][1] = acc[nt][2] = acc[nt][3] = 0.f;
        }
    }

    int r0 = n0 + wr * 16 + (lane >> 2);
    int r1 = r0 + 8;
    float s = 1.0f / (float)nChunks;
#pragma unroll
    for (int nt = 0; nt < 8; nt++) {
        int col = wc * 64 + nt * 8 + (lane & 3) * 2;
        if (r0 < NN) {
            float2 o = make_float2(fin[nt][0] * s, fin[nt][1] * s);
            *(float2*)(out + (size_t)r0 * 128 + col) = o;
        }
        if (r1 < NN) {
            float2 o = make_float2(fin[nt][2] * s, fin[nt][3] * s);
            *(float2*)(out + (size_t)r1 * 128 + col) = o;
        }
    }
}

// ---------------------------------------------------------------------------
extern "C" void kernel_launch(void* const* d_in, const int* in_sizes, int n_in,
                              void* d_out, int out_size) {
    const int*   gcn_src1 = (const int*)d_in[0];
    const int*   gcn_dst1 = (const int*)d_in[1];
    const int*   gcn_src2 = (const int*)d_in[2];
    const int*   gcn_dst2 = (const int*)d_in[3];
    const int*   rg_src1  = (const int*)d_in[4];
    const int*   rg_dst1  = (const int*)d_in[5];
    const int*   rg_et1   = (const int*)d_in[6];
    const int*   rg_src2  = (const int*)d_in[7];
    const int*   rg_dst2  = (const int*)d_in[8];
    const int*   rg_et2   = (const int*)d_in[9];
    const int*   het_src1 = (const int*)d_in[10];
    const int*   het_dst1 = (const int*)d_in[11];
    const int*   het_src2 = (const int*)d_in[12];
    const int*   het_dst2 = (const int*)d_in[13];
    const float* emb      = (const float*)d_in[14];
    const float* gcn_W1   = (const float*)d_in[15];
    const float* gcn_b1   = (const float*)d_in[16];
    const float* gcn_W2   = (const float*)d_in[17];
    const float* gcn_b2   = (const float*)d_in[18];
    const float* rg_W1    = (const float*)d_in[19];
    const float* rg_loop1 = (const float*)d_in[20];
    const float* rg_b1    = (const float*)d_in[21];
    const float* rg_W2    = (const float*)d_in[22];
    const float* rg_loop2 = (const float*)d_in[23];
    const float* rg_b2    = (const float*)d_in[24];
    const float* het_W1   = (const float*)d_in[25];
    const float* het_b1   = (const float*)d_in[26];
    const float* het_W2   = (const float*)d_in[27];
    const float* het_b2   = (const float*)d_in[28];

    float* out_hcf = (float*)d_out;
    float* out_hc  = out_hcf + (size_t)NN * D;
    float* out_hs  = out_hcf + (size_t)2 * NN * D;

    cudaFuncSetAttribute(tc_gemm32, cudaFuncAttributeMaxDynamicSharedMemorySize, SMEM_M32);
    cudaFuncSetAttribute(tc_gemm_mean, cudaFuncAttributeMaxDynamicSharedMemorySize, SMEM_BYTES);

    const int ZB = 256, ZG = 2048;
    const int sgrid = EH / 8;
    const int g32 = (NN + 127) / 128;   // 782
    const int g16 = (NN + 63) / 64;     // 1563

    prep_weights<<<28, 128>>>(gcn_W1, gcn_W2, rg_W1, rg_loop1, rg_W2, rg_loop2,
                              het_W1, het_W2);

    // ---- GCN branch ----
    zero_kernel<<<ZG, ZB>>>(2, NN * 32);
    scatter_kernel<<<sgrid, 256>>>(0, emb, gcn_src1, gcn_dst1, nullptr, 0, 1, 2, EH);
    tc_gemm32<<<g32, 256, SMEM_M32>>>(2, nullptr, 1, 0, 0, nullptr, -1, gcn_b1, nullptr, 1);
    zero_kernel<<<ZG, ZB>>>(2, NN * 32);
    scatter_kernel<<<sgrid, 256>>>(1, nullptr, gcn_src2, gcn_dst2, nullptr, 0, 1, 2, EH);
    tc_gemm32<<<g32, 256, SMEM_M32>>>(2, nullptr, 1, 1, 0, nullptr, -1, gcn_b2, out_hcf, 0);

    // ---- RGCN branch ----
    zero_kernel<<<ZG, ZB>>>(3, NN * RRG * 32);
    scatter_kernel<<<sgrid, 256>>>(0, emb, rg_src1, rg_dst1, rg_et1, 0, RRG, 3, EH);
    tc_gemm32<<<g32, 256, SMEM_M32>>>(3, nullptr, RRG, 2, 0, emb, 10, rg_b1, nullptr, 1);
    zero_kernel<<<ZG, ZB>>>(3, NN * RRG * 32);
    scatter_kernel<<<sgrid, 256>>>(1, nullptr, rg_src2, rg_dst2, rg_et2, 0, RRG, 3, EH);
    tc_gemm32<<<g32, 256, SMEM_M32>>>(3, nullptr, RRG, 11, 1, nullptr, 19, rg_b2, out_hc, 0);

    // ---- Hetero branch ----
    zero_kernel<<<ZG, ZB>>>(4, NN * RHET * 32);
    scatter_kernel<<<sgrid, 256>>>(0, emb, het_src1, het_dst1, nullptr, EREL, RHET, 4, EH);
    tc_gemm_mean<<<g16, 256, SMEM_BYTES>>>(4, RHET, 20, het_b1, nullptr, 1);
    zero_kernel<<<ZG, ZB>>>(4, NN * RHET * 32);
    scatter_kernel<<<sgrid, 256>>>(1, nullptr, het_src2, het_dst2, nullptr, EREL, RHET, 4, EH);
    tc_gemm_mean<<<g16, 256, SMEM_BYTES>>>(4, RHET, 24, het_b2, out_hs, 0);
}